// round 1
// baseline (speedup 1.0000x reference)
#include <cuda_runtime.h>
#include <math.h>

#define CB 2
#define CL 2048
#define CD 1024
#define CNH 16
#define CHD 64
#define CM (CB*CL)          // 4096 rows
#define CHGATE 256
#define CHNU 128

// ---------------- scratch (device globals; allocation-free rule) ----------------
__device__ float g_pool[CM*CD];
__device__ float g_Q[CM*CD];
__device__ float g_K[CM*CD];
__device__ float g_V[CM*CD];
__device__ float g_gk[CM*CD];
__device__ float g_zglu[CM*CD];
__device__ float g_U[CM*CD];
__device__ float g_Gg[CM*CD];     // GLU gate branch; reused for adv_n
__device__ float g_ao[CM*CD];     // attention output
__device__ float g_gb[CB*CL*CL];  // coherence bias
__device__ float g_S[134217728];  // (B,NH,L,L) logits/probs  = 536 MB
__device__ float g_gate[CM];
__device__ float g_nu[CM];
__device__ double g_invd[1536];   // inv freqs: [fast | slow | glu] x 512

// ---------------- rope helpers ----------------
__global__ void inv_kernel() {
    int d = threadIdx.x;                      // 512 threads
    double e = (double)(2 * d) / (double)CD;
    g_invd[d]        = pow(1.6180339887498948482, -e);
    g_invd[512 + d]  = pow(1618.0, -e);
    g_invd[1024 + d] = pow(16180.0, -e);
}

__device__ __forceinline__ void rope_cs(double inv, int t, float* c, float* s) {
    double ang = (double)t * inv;
    double k = floor(ang * 0.15915494309189533576888376337251436);
    float a = (float)(ang - k * 6.28318530717958647692528676655900577);
    sincosf(a, s, c);
}

// ---------------- causal cumulative mean ----------------
__global__ void pool_kernel(const float* __restrict__ z) {
    int d = blockIdx.x * blockDim.x + threadIdx.x;   // 0..1023
    int b = blockIdx.y;
    const float* zp = z + (size_t)b * CL * CD + d;
    float* pp = g_pool + (size_t)b * CL * CD + d;
    float acc = 0.f;
    for (int l = 0; l < CL; l++) {
        acc += zp[(size_t)l * CD];
        pp[(size_t)l * CD] = acc / (float)(l + 1);
    }
}

// ---------------- generic 128x128x8 SGEMM: C = A@W (+bias) ----------------
// MODE 0: C = A@W + bias (bias may be null)
// MODE 1: C = r1 + 0.42*r2 + 1.07*(A@W + bias)   (final output)
template<int MODE>
__global__ __launch_bounds__(256) void sgemm_nn(
    const float* __restrict__ A, const float* __restrict__ W,
    const float* __restrict__ bias, float* __restrict__ C,
    int M, int N, int K,
    const float* __restrict__ r1, const float* __restrict__ r2)
{
    __shared__ float As[8][128];
    __shared__ float Bs[8][128];
    const int tid = threadIdx.x;
    const int bm = blockIdx.y * 128;
    const int bn = blockIdx.x * 128;
    const int arow = tid >> 1;
    const int acol = (tid & 1) * 4;
    const int brow = tid >> 5;
    const int bcol = (tid & 31) * 4;
    const int ty = tid >> 4, tx = tid & 15;
    const float* Ap = A + (size_t)(bm + arow) * K + acol;
    const float* Wp = W + (size_t)brow * N + bn + bcol;
    float acc[8][8];
#pragma unroll
    for (int i = 0; i < 8; i++)
#pragma unroll
        for (int j = 0; j < 8; j++) acc[i][j] = 0.f;

    for (int k0 = 0; k0 < K; k0 += 8) {
        float4 av = *(const float4*)(Ap + k0);
        float4 bv = *(const float4*)(Wp + (size_t)k0 * N);
        As[acol + 0][arow] = av.x;
        As[acol + 1][arow] = av.y;
        As[acol + 2][arow] = av.z;
        As[acol + 3][arow] = av.w;
        *(float4*)&Bs[brow][bcol] = bv;
        __syncthreads();
#pragma unroll
        for (int k = 0; k < 8; k++) {
            float4 a0 = *(const float4*)&As[k][ty * 8];
            float4 a1 = *(const float4*)&As[k][ty * 8 + 4];
            float4 b0 = *(const float4*)&Bs[k][tx * 8];
            float4 b1 = *(const float4*)&Bs[k][tx * 8 + 4];
            float aa[8] = {a0.x, a0.y, a0.z, a0.w, a1.x, a1.y, a1.z, a1.w};
            float bb[8] = {b0.x, b0.y, b0.z, b0.w, b1.x, b1.y, b1.z, b1.w};
#pragma unroll
            for (int i = 0; i < 8; i++)
#pragma unroll
                for (int j = 0; j < 8; j++)
                    acc[i][j] += aa[i] * bb[j];
        }
        __syncthreads();
    }
#pragma unroll
    for (int i = 0; i < 8; i++) {
        int m = bm + ty * 8 + i;
#pragma unroll
        for (int j = 0; j < 8; j++) {
            int n = bn + tx * 8 + j;
            float v = acc[i][j];
            if (MODE == 0) {
                if (bias) v += bias[n];
                C[(size_t)m * N + n] = v;
            } else {
                v += bias[n];
                C[(size_t)m * N + n] =
                    r1[(size_t)m * N + n] + 0.42f * r2[(size_t)m * N + n] + 1.07f * v;
            }
        }
    }
}

// ---------------- NT GEMM (both operands row-major LxD slices) ----------------
// MODE 0 (coherence bias): C[b,l,m] = tanh(gamma)/32 * dot(gk[b,l,:], K[b,m,:]), z = b
// MODE 1 (logits):         C[b,h,l,m] = 0.125*dot(Qr_h, Kr_h) + gb[b,l,m], z = b*NH+h
template<int MODE>
__global__ __launch_bounds__(256) void sgemm_nt(
    const float* __restrict__ Abase, const float* __restrict__ Bbase,
    float* __restrict__ Cbase, const float* __restrict__ gamma,
    const float* __restrict__ gbbase)
{
    const int bm = blockIdx.y * 128;
    const int bn = blockIdx.x * 128;
    if (MODE == 1 && bn >= bm + 128) return;   // fully masked block
    const int bz = blockIdx.z;
    const float* A; const float* B2; float* C; const float* gbr = nullptr;
    int Kk, lda;
    if (MODE == 0) {
        A  = Abase + (size_t)bz * CL * CD;
        B2 = Bbase + (size_t)bz * CL * CD;
        C  = Cbase + (size_t)bz * CL * CL;
        Kk = CD; lda = CD;
    } else {
        int b = bz >> 4, h = bz & 15;
        A  = Abase + (size_t)b * CL * CD + h * CHD;
        B2 = Bbase + (size_t)b * CL * CD + h * CHD;
        C  = Cbase + (size_t)bz * CL * CL;
        gbr = gbbase + (size_t)b * CL * CL;
        Kk = CHD; lda = CD;
    }
    __shared__ float As[8][128];
    __shared__ float Bs[8][128];
    const int tid = threadIdx.x;
    const int r4 = tid >> 1;
    const int c4 = (tid & 1) * 4;
    const int ty = tid >> 4, tx = tid & 15;
    float acc[8][8];
#pragma unroll
    for (int i = 0; i < 8; i++)
#pragma unroll
        for (int j = 0; j < 8; j++) acc[i][j] = 0.f;

    for (int k0 = 0; k0 < Kk; k0 += 8) {
        float4 av = *(const float4*)(A + (size_t)(bm + r4) * lda + k0 + c4);
        float4 bv = *(const float4*)(B2 + (size_t)(bn + r4) * lda + k0 + c4);
        As[c4 + 0][r4] = av.x; As[c4 + 1][r4] = av.y;
        As[c4 + 2][r4] = av.z; As[c4 + 3][r4] = av.w;
        Bs[c4 + 0][r4] = bv.x; Bs[c4 + 1][r4] = bv.y;
        Bs[c4 + 2][r4] = bv.z; Bs[c4 + 3][r4] = bv.w;
        __syncthreads();
#pragma unroll
        for (int k = 0; k < 8; k++) {
            float4 a0 = *(const float4*)&As[k][ty * 8];
            float4 a1 = *(const float4*)&As[k][ty * 8 + 4];
            float4 b0 = *(const float4*)&Bs[k][tx * 8];
            float4 b1 = *(const float4*)&Bs[k][tx * 8 + 4];
            float aa[8] = {a0.x, a0.y, a0.z, a0.w, a1.x, a1.y, a1.z, a1.w};
            float bb[8] = {b0.x, b0.y, b0.z, b0.w, b1.x, b1.y, b1.z, b1.w};
#pragma unroll
            for (int i = 0; i < 8; i++)
#pragma unroll
                for (int j = 0; j < 8; j++)
                    acc[i][j] += aa[i] * bb[j];
        }
        __syncthreads();
    }
    float scale = (MODE == 0) ? tanhf(gamma[0]) * 0.03125f : 0.125f;
#pragma unroll
    for (int i = 0; i < 8; i++) {
        int m = bm + ty * 8 + i;
#pragma unroll
        for (int j = 0; j < 8; j++) {
            int n = bn + tx * 8 + j;
            float v = acc[i][j] * scale;
            if (MODE == 1) v += gbr[(size_t)m * CL + n];
            C[(size_t)m * CL + n] = v;
        }
    }
}

// ---------------- gate MLP (H=256) ----------------
__global__ __launch_bounds__(256) void gate_kernel(
    const float* __restrict__ w1, const float* __restrict__ b1,
    const float* __restrict__ w2, const float* __restrict__ b2)
{
    __shared__ float ps[8][1024];
    __shared__ float red[256];
    const int tid = threadIdx.x;
    const int r0 = blockIdx.x * 8;
    for (int i = tid; i < 8 * 1024; i += 256)
        ps[i >> 10][i & 1023] = g_pool[(size_t)r0 * CD + i];
    __syncthreads();
    float acc[8];
#pragma unroll
    for (int r = 0; r < 8; r++) acc[r] = 0.f;
    for (int k = 0; k < CD; k++) {
        float w = w1[(size_t)k * CHGATE + tid];
#pragma unroll
        for (int r = 0; r < 8; r++) acc[r] = fmaf(ps[r][k], w, acc[r]);
    }
    float bb = b1[tid];
    float w2v = w2[tid];
    for (int r = 0; r < 8; r++) {
        float x = acc[r] + bb;
        float h = 0.5f * x * (1.f + erff(x * 0.7071067811865476f));
        red[tid] = h * w2v;
        __syncthreads();
        for (int s = 128; s > 0; s >>= 1) {
            if (tid < s) red[tid] += red[tid + s];
            __syncthreads();
        }
        if (tid == 0) {
            float y = red[0] + b2[0];
            g_gate[r0 + r] = 1.f / (1.f + expf(-y));
        }
        __syncthreads();
    }
}

// ---------------- viscosity MLP (H=128) ----------------
__global__ __launch_bounds__(128) void nu_kernel(
    const float* __restrict__ w1, const float* __restrict__ b1,
    const float* __restrict__ w2, const float* __restrict__ b2,
    const float* __restrict__ nu_diff, const float* __restrict__ nu_adv)
{
    __shared__ float ps[8][1024];
    __shared__ float red[128];
    const int tid = threadIdx.x;
    const int r0 = blockIdx.x * 8;
    for (int i = tid; i < 8 * 1024; i += 128)
        ps[i >> 10][i & 1023] = g_pool[(size_t)r0 * CD + i];
    __syncthreads();
    float acc[8];
#pragma unroll
    for (int r = 0; r < 8; r++) acc[r] = 0.f;
    for (int k = 0; k < CD; k++) {
        float w = w1[(size_t)k * CHNU + tid];
#pragma unroll
        for (int r = 0; r < 8; r++) acc[r] = fmaf(ps[r][k], w, acc[r]);
    }
    float bb = b1[tid];
    float w2v = w2[tid];
    float nd = fabsf(nu_diff[0]), na = fabsf(nu_adv[0]);
    for (int r = 0; r < 8; r++) {
        float h = tanhf(acc[r] + bb);
        red[tid] = h * w2v;
        __syncthreads();
        for (int s = 64; s > 0; s >>= 1) {
            if (tid < s) red[tid] += red[tid + s];
            __syncthreads();
        }
        if (tid == 0)
            g_nu[r0 + r] = nd + tanhf(red[0] + b2[0]) * na;
        __syncthreads();
    }
}

// ---------------- RoPE (in-place on Q,K; blended gate) ----------------
__global__ void rope_qk_kernel() {
    int idx = blockIdx.x * blockDim.x + threadIdx.x;
    if (idx >= CM * 512) return;
    int d = idx & 511;
    int row = idx >> 9;
    int t = row & (CL - 1);
    float g = g_gate[row];
    float cf, sf, c2, s2;
    rope_cs(g_invd[d], t, &cf, &sf);
    rope_cs(g_invd[512 + d], t, &c2, &s2);
    float c = g * cf + (1.f - g) * c2;
    float s = g * sf + (1.f - g) * s2;
    size_t lo = (size_t)row * CD + d, hi = lo + 512;
    float ql = g_Q[lo], qh = g_Q[hi];
    g_Q[lo] = ql * c - qh * s;
    g_Q[hi] = qh * c + ql * s;
    float kl = g_K[lo], kh = g_K[hi];
    g_K[lo] = kl * c - kh * s;
    g_K[hi] = kh * c + kl * s;
}

__global__ void rope_glu_kernel(const float* __restrict__ z) {
    int idx = blockIdx.x * blockDim.x + threadIdx.x;
    if (idx >= CM * 512) return;
    int d = idx & 511;
    int row = idx >> 9;
    int t = row & (CL - 1);
    float c, s;
    rope_cs(g_invd[1024 + d], t, &c, &s);
    size_t lo = (size_t)row * CD + d, hi = lo + 512;
    float xl = z[lo], xh = z[hi];
    g_zglu[lo] = xl * c - xh * s;
    g_zglu[hi] = xh * c + xl * s;
}

// ---------------- causal softmax (in-place on g_S rows) ----------------
__global__ __launch_bounds__(256) void softmax_kernel() {
    int gr = blockIdx.x;                   // b*NH*L + h*L + l
    int l = gr & (CL - 1);
    float* row = g_S + (size_t)gr * CL;
    int n = l + 1;
    __shared__ float buf[CL];
    __shared__ float red[256];
    int tid = threadIdx.x;
    float mx = -3.4e38f;
    for (int i = tid; i < n; i += 256) { float v = row[i]; buf[i] = v; mx = fmaxf(mx, v); }
    red[tid] = mx; __syncthreads();
    for (int s = 128; s > 0; s >>= 1) {
        if (tid < s) red[tid] = fmaxf(red[tid], red[tid + s]);
        __syncthreads();
    }
    mx = red[0]; __syncthreads();
    float sum = 0.f;
    for (int i = tid; i < n; i += 256) { float e = expf(buf[i] - mx); buf[i] = e; sum += e; }
    red[tid] = sum; __syncthreads();
    for (int s = 128; s > 0; s >>= 1) {
        if (tid < s) red[tid] += red[tid + s];
        __syncthreads();
    }
    float rinv = 1.f / red[0];
    int bound = ((l >> 6) + 1) << 6;       // zero-fill up to the diagonal 64-block edge
    for (int i = tid; i < n; i += 256) row[i] = buf[i] * rinv;
    for (int i = n + tid; i < bound; i += 256) row[i] = 0.f;
}

// ---------------- attn_w = mean over heads ----------------
__global__ void awmean_kernel(float* __restrict__ aw) {
    size_t idx = (size_t)blockIdx.x * blockDim.x + threadIdx.x;
    const size_t tot = (size_t)CB * CL * CL;
    if (idx >= tot) return;
    size_t b = idx / ((size_t)CL * CL);
    size_t rem = idx - b * (size_t)CL * CL;
    int l = (int)(rem >> 11);
    int m = (int)(rem & (CL - 1));
    if (m > l) { aw[idx] = 0.f; return; }
    const float* p = g_S + b * (size_t)CNH * CL * CL + rem;
    float s = 0.f;
#pragma unroll
    for (int hh = 0; hh < CNH; hh++) s += p[(size_t)hh * CL * CL];
    aw[idx] = s * (1.f / CNH);
}

// ---------------- attn_out = probs @ V (per 64-row tile, per head) ----------------
__global__ __launch_bounds__(256) void attnout_kernel() {
    int l0 = blockIdx.x * 64;
    int h = blockIdx.y, b = blockIdx.z;
    const float* S = g_S + ((size_t)(b * CNH + h)) * CL * CL;
    const float* V = g_V + (size_t)b * CL * CD + h * CHD;
    float* O = g_ao + (size_t)b * CL * CD + h * CHD;
    __shared__ float Ps[64][68];
    __shared__ float Vs[64][68];
    int tid = threadIdx.x;
    int ty = tid >> 4, tx = tid & 15;
    int lr = tid >> 2, lc = (tid & 3) * 16;
    float acc[4][4];
#pragma unroll
    for (int i = 0; i < 4; i++)
#pragma unroll
        for (int j = 0; j < 4; j++) acc[i][j] = 0.f;

    for (int m0 = 0; m0 <= l0; m0 += 64) {
        const float* sp = S + (size_t)(l0 + lr) * CL + m0 + lc;
        float4 v0 = *(const float4*)sp;
        float4 v1 = *(const float4*)(sp + 4);
        float4 v2 = *(const float4*)(sp + 8);
        float4 v3 = *(const float4*)(sp + 12);
        *(float4*)&Ps[lr][lc]      = v0;
        *(float4*)&Ps[lr][lc + 4]  = v1;
        *(float4*)&Ps[lr][lc + 8]  = v2;
        *(float4*)&Ps[lr][lc + 12] = v3;
        const float* vp = V + (size_t)(m0 + lr) * CD + lc;
        float4 w0 = *(const float4*)vp;
        float4 w1 = *(const float4*)(vp + 4);
        float4 w2 = *(const float4*)(vp + 8);
        float4 w3 = *(const float4*)(vp + 12);
        *(float4*)&Vs[lr][lc]      = w0;
        *(float4*)&Vs[lr][lc + 4]  = w1;
        *(float4*)&Vs[lr][lc + 8]  = w2;
        *(float4*)&Vs[lr][lc + 12] = w3;
        __syncthreads();
#pragma unroll 8
        for (int k = 0; k < 64; k++) {
            float a0 = Ps[ty * 4 + 0][k];
            float a1 = Ps[ty * 4 + 1][k];
            float a2 = Ps[ty * 4 + 2][k];
            float a3 = Ps[ty * 4 + 3][k];
            float4 bv = *(const float4*)&Vs[k][tx * 4];
            acc[0][0] += a0 * bv.x; acc[0][1] += a0 * bv.y; acc[0][2] += a0 * bv.z; acc[0][3] += a0 * bv.w;
            acc[1][0] += a1 * bv.x; acc[1][1] += a1 * bv.y; acc[1][2] += a1 * bv.z; acc[1][3] += a1 * bv.w;
            acc[2][0] += a2 * bv.x; acc[2][1] += a2 * bv.y; acc[2][2] += a2 * bv.z; acc[2][3] += a2 * bv.w;
            acc[3][0] += a3 * bv.x; acc[3][1] += a3 * bv.y; acc[3][2] += a3 * bv.z; acc[3][3] += a3 * bv.w;
        }
        __syncthreads();
    }
#pragma unroll
    for (int i = 0; i < 4; i++)
#pragma unroll
        for (int j = 0; j < 4; j++)
            O[(size_t)(l0 + ty * 4 + i) * CD + tx * 4 + j] = acc[i][j];
}

// ---------------- bilinear * (-nu) + LayerNorm (writes adv_n into g_U) ----------------
__global__ __launch_bounds__(256) void bilin_ln_kernel(
    const float* __restrict__ ln_w, const float* __restrict__ ln_b)
{
    int row = blockIdx.x;
    int tid = threadIdx.x;
    size_t off = (size_t)row * CD;
    float nu = g_nu[row];                     // ALPHA_ADV = 1.0
    __shared__ float red[256], red2[256];
    float a[4]; float s = 0.f, s2 = 0.f;
#pragma unroll
    for (int i = 0; i < 4; i++) {
        int d = tid + i * 256;
        float v = -nu * g_U[off + d] * g_Gg[off + d];
        a[i] = v; s += v; s2 += v * v;
    }
    red[tid] = s; red2[tid] = s2; __syncthreads();
    for (int st = 128; st > 0; st >>= 1) {
        if (tid < st) { red[tid] += red[tid + st]; red2[tid] += red2[tid + st]; }
        __syncthreads();
    }
    float mu = red[0] * (1.f / CD);
    float var = red2[0] * (1.f / CD) - mu * mu;
    float rstd = rsqrtf(var + 1e-5f);
#pragma unroll
    for (int i = 0; i < 4; i++) {
        int d = tid + i * 256;
        g_U[off + d] = (a[i] - mu) * rstd * ln_w[d] + ln_b[d];
    }
}

// ---------------- launcher ----------------
extern "C" void kernel_launch(void* const* d_in, const int* in_sizes, int n_in,
                              void* d_out, int out_size) {
    (void)in_sizes; (void)n_in; (void)out_size;
    const float* z     = (const float*)d_in[0];
    const float* Wq    = (const float*)d_in[1];
    const float* bq    = (const float*)d_in[2];
    const float* Wk    = (const float*)d_in[3];
    const float* bk    = (const float*)d_in[4];
    const float* Wv    = (const float*)d_in[5];
    const float* bv    = (const float*)d_in[6];
    const float* Wcoh  = (const float*)d_in[7];
    const float* gamma = (const float*)d_in[8];
    const float* rg_w1 = (const float*)d_in[9];
    const float* rg_b1 = (const float*)d_in[10];
    const float* rg_w2 = (const float*)d_in[11];
    const float* rg_b2 = (const float*)d_in[12];
    const float* nu_diff = (const float*)d_in[13];
    const float* nu_adv  = (const float*)d_in[14];
    const float* nu_w1 = (const float*)d_in[15];
    const float* nu_b1 = (const float*)d_in[16];
    const float* nu_w2 = (const float*)d_in[17];
    const float* nu_b2 = (const float*)d_in[18];
    const float* Wu    = (const float*)d_in[19];
    const float* bu    = (const float*)d_in[20];
    const float* Wg    = (const float*)d_in[21];
    const float* bg    = (const float*)d_in[22];
    const float* ln_w  = (const float*)d_in[23];
    const float* ln_b  = (const float*)d_in[24];
    const float* Cw    = (const float*)d_in[25];
    const float* Cb    = (const float*)d_in[26];

    float* out_z  = (float*)d_out;
    float* out_aw = out_z + (size_t)CM * CD;

    void* tmp;
    cudaGetSymbolAddress(&tmp, g_pool); float* pPool = (float*)tmp;
    cudaGetSymbolAddress(&tmp, g_Q);    float* pQ    = (float*)tmp;
    cudaGetSymbolAddress(&tmp, g_K);    float* pK    = (float*)tmp;
    cudaGetSymbolAddress(&tmp, g_V);    float* pV    = (float*)tmp; (void)pV;
    cudaGetSymbolAddress(&tmp, g_gk);   float* pGk   = (float*)tmp;
    cudaGetSymbolAddress(&tmp, g_zglu); float* pZg   = (float*)tmp;
    cudaGetSymbolAddress(&tmp, g_U);    float* pU    = (float*)tmp;
    cudaGetSymbolAddress(&tmp, g_Gg);   float* pG    = (float*)tmp;
    cudaGetSymbolAddress(&tmp, g_ao);   float* pAo   = (float*)tmp;
    cudaGetSymbolAddress(&tmp, g_gb);   float* pGb   = (float*)tmp;
    cudaGetSymbolAddress(&tmp, g_S);    float* pS    = (float*)tmp;

    dim3 gmain(CD / 128, CM / 128);   // (8, 32)

    inv_kernel<<<1, 512>>>();
    pool_kernel<<<dim3(CD / 256, CB), 256>>>(z);

    sgemm_nn<0><<<gmain, 256>>>(z, Wq, bq, pQ, CM, CD, CD, nullptr, nullptr);
    sgemm_nn<0><<<gmain, 256>>>(z, Wk, bk, pK, CM, CD, CD, nullptr, nullptr);
    sgemm_nn<0><<<gmain, 256>>>(z, Wv, bv, pV, CM, CD, CD, nullptr, nullptr);
    sgemm_nn<0><<<gmain, 256>>>(pPool, Wcoh, nullptr, pGk, CM, CD, CD, nullptr, nullptr);

    gate_kernel<<<CM / 8, 256>>>(rg_w1, rg_b1, rg_w2, rg_b2);
    nu_kernel<<<CM / 8, 128>>>(nu_w1, nu_b1, nu_w2, nu_b2, nu_diff, nu_adv);

    // coherence bias uses pre-rope K
    sgemm_nt<0><<<dim3(CL / 128, CL / 128, CB), 256>>>(pGk, pK, pGb, gamma, nullptr);

    rope_qk_kernel<<<(CM * 512) / 256, 256>>>();
    rope_glu_kernel<<<(CM * 512) / 256, 256>>>(z);

    sgemm_nn<0><<<gmain, 256>>>(pZg, Wu, bu, pU, CM, CD, CD, nullptr, nullptr);
    sgemm_nn<0><<<gmain, 256>>>(pZg, Wg, bg, pG, CM, CD, CD, nullptr, nullptr);

    // logits for all heads (post-rope Q/K), causal block skip
    sgemm_nt<1><<<dim3(CL / 128, CL / 128, CB * CNH), 256>>>(pQ, pK, pS, nullptr, pGb);
    softmax_kernel<<<CB * CNH * CL, 256>>>();
    awmean_kernel<<<(CB * CL * CL) / 256, 256>>>(out_aw);
    attnout_kernel<<<dim3(CL / 64, CNH, CB), 256>>>();

    bilin_ln_kernel<<<CM, 256>>>(ln_w, ln_b);
    // final: out = z + 0.42*attn_out + 1.07*(adv_n @ Cw + Cb)
    sgemm_nn<1><<<gmain, 256>>>(pU, Cw, Cb, out_z, CM, CD, CD, z, pAo);
}

// round 2
// speedup vs baseline: 1.0307x; 1.0307x over previous
#include <cuda_runtime.h>
#include <math.h>
#include <stdint.h>

#define CB 2
#define CL 2048
#define CD 1024
#define CNH 16
#define CHD 64
#define CM (CB*CL)          // 4096 rows
#define CHGATE 256
#define CHNU 128

// ---------------- scratch (device globals; allocation-free rule) ----------------
__device__ float g_pool[CM*CD];
__device__ float g_Q[CM*CD];
__device__ float g_K[CM*CD];
__device__ float g_V[CM*CD];
__device__ float g_gk[CM*CD];
__device__ float g_zglu[CM*CD];
__device__ float g_U[CM*CD];
__device__ float g_Gg[CM*CD];     // GLU gate branch
__device__ float g_ao[CM*CD];     // attention output
__device__ float g_gb[CB*CL*CL];  // coherence bias
__device__ float g_S[134217728];  // (B,NH,L,L) logits/probs  = 536 MB
__device__ float g_gate[CM];
__device__ float g_nu[CM];
__device__ double g_invd[1536];   // inv freqs: [fast | slow | glu] x 512

// ---------------- tf32 tensor-core helpers ----------------
__device__ __forceinline__ unsigned f2tf(float x) {
    unsigned r; asm("cvt.rna.tf32.f32 %0, %1;" : "=r"(r) : "f"(x)); return r;
}
__device__ __forceinline__ void cpa16(float* s, const float* g) {
    unsigned sa = (unsigned)__cvta_generic_to_shared(s);
    asm volatile("cp.async.cg.shared.global [%0], [%1], 16;" :: "r"(sa), "l"(g));
}
__device__ __forceinline__ void mma8(float* d, const unsigned* a, const unsigned* b) {
    asm volatile(
        "mma.sync.aligned.m16n8k8.row.col.f32.tf32.tf32.f32 "
        "{%0,%1,%2,%3},{%4,%5,%6,%7},{%8,%9},{%0,%1,%2,%3};"
        : "+f"(d[0]), "+f"(d[1]), "+f"(d[2]), "+f"(d[3])
        : "r"(a[0]), "r"(a[1]), "r"(a[2]), "r"(a[3]), "r"(b[0]), "r"(b[1]));
}

// ---------------- tensor-core GEMM: 128x128x32 tiles, tf32 ----------------
// TB=0: C = A[M,K] @ B[K,N]          TB=1: C = A[M,K] @ B[N,K]^T
// MODE 0: C = acc + bias(optional)
// MODE 1: C = r1 + 0.42*r2 + 1.07*(acc + bias)     (final combine)
// MODE 2: C = tanh(gamma)/32 * acc                 (coherence bias)
// MODE 3: C = 0.125*acc + gb[l,m], causal blockskip (logits)
template<int TB, int MODE>
__global__ __launch_bounds__(256) void tc_gemm(
    const float* __restrict__ A, const float* __restrict__ Bm,
    const float* __restrict__ bias, float* __restrict__ C,
    int K, int lda, int ldb, int ldc,
    long sAo, long sAi, long sBo, long sBi, long sCz, long sGo, int zdiv,
    const float* __restrict__ r1, const float* __restrict__ r2,
    const float* __restrict__ gamma, const float* __restrict__ gbb)
{
    const int bm = blockIdx.y * 128, bn = blockIdx.x * 128;
    if (MODE == 3 && bn >= bm + 128) return;   // fully masked causal block
    const int z = blockIdx.z;
    const int zo = z / zdiv, zi = z - zo * zdiv;
    A  += (size_t)zo * sAo + (size_t)zi * sAi;
    Bm += (size_t)zo * sBo + (size_t)zi * sBi;
    C  += (size_t)z * sCz;
    const float* gbp = (MODE == 3) ? (gbb + (size_t)zo * sGo) : nullptr;

    extern __shared__ float sm[];
    const int STG = 9216;                       // floats per stage
    float* Asm[2] = { sm, sm + STG };
    float* Bsm[2] = { sm + 4608, sm + STG + 4608 };

    const int t = threadIdx.x;
    const int wid = t >> 5, lane = t & 31;
    const int wm = (wid >> 2) * 64, wn = (wid & 3) * 32;
    const int g = lane >> 2, tig = lane & 3;

    float acc[4][4][4];
#pragma unroll
    for (int i = 0; i < 4; i++)
#pragma unroll
        for (int j = 0; j < 4; j++)
#pragma unroll
            for (int q = 0; q < 4; q++) acc[i][j][q] = 0.f;

    auto loadA = [&](float* s, int k0) {
        int r = t >> 3, k4 = (t & 7) * 4;
#pragma unroll
        for (int it = 0; it < 4; it++)
            cpa16(s + (r + it*32)*36 + k4,
                  A + (size_t)(bm + r + it*32) * lda + k0 + k4);
    };
    auto loadB = [&](float* s, int k0) {
        if (TB == 0) {
            int k = t >> 5, n4 = (t & 31) * 4;
#pragma unroll
            for (int it = 0; it < 4; it++)
                cpa16(s + (k + it*8)*136 + n4,
                      Bm + (size_t)(k0 + k + it*8) * ldb + bn + n4);
        } else {
            int r = t >> 3, k4 = (t & 7) * 4;
#pragma unroll
            for (int it = 0; it < 4; it++)
                cpa16(s + (r + it*32)*36 + k4,
                      Bm + (size_t)(bn + r + it*32) * ldb + k0 + k4);
        }
    };

    const int NT = K >> 5;
    loadA(Asm[0], 0); loadB(Bsm[0], 0);
    asm volatile("cp.async.commit_group;");

    for (int kt = 0; kt < NT; kt++) {
        if (kt + 1 < NT) {
            loadA(Asm[(kt+1)&1], (kt+1)*32);
            loadB(Bsm[(kt+1)&1], (kt+1)*32);
            asm volatile("cp.async.commit_group;");
            asm volatile("cp.async.wait_group 1;");
        } else {
            asm volatile("cp.async.wait_group 0;");
        }
        __syncthreads();
        const float* Ab = Asm[kt&1];
        const float* Bb = Bsm[kt&1];
#pragma unroll
        for (int ks = 0; ks < 4; ks++) {
            const int k = ks * 8;
            unsigned af[4][4];
#pragma unroll
            for (int i = 0; i < 4; i++) {
                const float* ap = Ab + (wm + 16*i + g)*36 + k + tig;
                af[i][0] = f2tf(ap[0]);
                af[i][1] = f2tf(ap[8*36]);
                af[i][2] = f2tf(ap[4]);
                af[i][3] = f2tf(ap[8*36 + 4]);
            }
            unsigned bf[4][2];
#pragma unroll
            for (int j = 0; j < 4; j++) {
                if (TB == 0) {
                    const float* bp = Bb + (k + tig)*136 + wn + 8*j + g;
                    bf[j][0] = f2tf(bp[0]);
                    bf[j][1] = f2tf(bp[4*136]);
                } else {
                    const float* bp = Bb + (wn + 8*j + g)*36 + k + tig;
                    bf[j][0] = f2tf(bp[0]);
                    bf[j][1] = f2tf(bp[4]);
                }
            }
#pragma unroll
            for (int i = 0; i < 4; i++)
#pragma unroll
                for (int j = 0; j < 4; j++)
                    mma8(acc[i][j], af[i], bf[j]);
        }
        __syncthreads();
    }

    float scale = 1.f;
    if (MODE == 2) scale = tanhf(gamma[0]) * 0.03125f;
    if (MODE == 3) scale = 0.125f;
#pragma unroll
    for (int i = 0; i < 4; i++) {
        const int r0 = bm + wm + 16*i + g;
#pragma unroll
        for (int j = 0; j < 4; j++) {
            const int c0 = bn + wn + 8*j + 2*tig;
#pragma unroll
            for (int h2 = 0; h2 < 2; h2++) {
                const int rr = r0 + h2*8;
                float v0 = acc[i][j][h2*2], v1 = acc[i][j][h2*2+1];
                const size_t off = (size_t)rr * ldc + c0;
                if (MODE == 0) {
                    if (bias) { v0 += bias[c0]; v1 += bias[c0+1]; }
                    C[off] = v0; C[off+1] = v1;
                } else if (MODE == 1) {
                    C[off]   = r1[off]   + 0.42f*r2[off]   + 1.07f*(v0 + bias[c0]);
                    C[off+1] = r1[off+1] + 0.42f*r2[off+1] + 1.07f*(v1 + bias[c0+1]);
                } else if (MODE == 2) {
                    C[off] = v0*scale; C[off+1] = v1*scale;
                } else {
                    const size_t go = (size_t)rr * CL + c0;
                    C[off]   = v0*scale + gbp[go];
                    C[off+1] = v1*scale + gbp[go+1];
                }
            }
        }
    }
}

// ---------------- rope helpers ----------------
__global__ void inv_kernel() {
    int d = threadIdx.x;                      // 512 threads
    double e = (double)(2 * d) / (double)CD;
    g_invd[d]        = pow(1.6180339887498948482, -e);
    g_invd[512 + d]  = pow(1618.0, -e);
    g_invd[1024 + d] = pow(16180.0, -e);
}

__device__ __forceinline__ void rope_cs(double inv, int t, float* c, float* s) {
    double ang = (double)t * inv;
    double k = floor(ang * 0.15915494309189533576888376337251436);
    float a = (float)(ang - k * 6.28318530717958647692528676655900577);
    sincosf(a, s, c);
}

// ---------------- causal cumulative mean ----------------
__global__ void pool_kernel(const float* __restrict__ z) {
    int d = blockIdx.x * blockDim.x + threadIdx.x;
    int b = blockIdx.y;
    const float* zp = z + (size_t)b * CL * CD + d;
    float* pp = g_pool + (size_t)b * CL * CD + d;
    float acc = 0.f;
    for (int l = 0; l < CL; l++) {
        acc += zp[(size_t)l * CD];
        pp[(size_t)l * CD] = acc / (float)(l + 1);
    }
}

// ---------------- gate MLP (H=256) ----------------
__global__ __launch_bounds__(256) void gate_kernel(
    const float* __restrict__ w1, const float* __restrict__ b1,
    const float* __restrict__ w2, const float* __restrict__ b2)
{
    __shared__ float ps[8][1024];
    __shared__ float red[256];
    const int tid = threadIdx.x;
    const int r0 = blockIdx.x * 8;
    for (int i = tid; i < 8 * 1024; i += 256)
        ps[i >> 10][i & 1023] = g_pool[(size_t)r0 * CD + i];
    __syncthreads();
    float acc[8];
#pragma unroll
    for (int r = 0; r < 8; r++) acc[r] = 0.f;
    for (int k = 0; k < CD; k++) {
        float w = w1[(size_t)k * CHGATE + tid];
#pragma unroll
        for (int r = 0; r < 8; r++) acc[r] = fmaf(ps[r][k], w, acc[r]);
    }
    float bb = b1[tid];
    float w2v = w2[tid];
    for (int r = 0; r < 8; r++) {
        float x = acc[r] + bb;
        float h = 0.5f * x * (1.f + erff(x * 0.7071067811865476f));
        red[tid] = h * w2v;
        __syncthreads();
        for (int s = 128; s > 0; s >>= 1) {
            if (tid < s) red[tid] += red[tid + s];
            __syncthreads();
        }
        if (tid == 0) {
            float y = red[0] + b2[0];
            g_gate[r0 + r] = 1.f / (1.f + expf(-y));
        }
        __syncthreads();
    }
}

// ---------------- viscosity MLP (H=128) ----------------
__global__ __launch_bounds__(128) void nu_kernel(
    const float* __restrict__ w1, const float* __restrict__ b1,
    const float* __restrict__ w2, const float* __restrict__ b2,
    const float* __restrict__ nu_diff, const float* __restrict__ nu_adv)
{
    __shared__ float ps[8][1024];
    __shared__ float red[128];
    const int tid = threadIdx.x;
    const int r0 = blockIdx.x * 8;
    for (int i = tid; i < 8 * 1024; i += 128)
        ps[i >> 10][i & 1023] = g_pool[(size_t)r0 * CD + i];
    __syncthreads();
    float acc[8];
#pragma unroll
    for (int r = 0; r < 8; r++) acc[r] = 0.f;
    for (int k = 0; k < CD; k++) {
        float w = w1[(size_t)k * CHNU + tid];
#pragma unroll
        for (int r = 0; r < 8; r++) acc[r] = fmaf(ps[r][k], w, acc[r]);
    }
    float bb = b1[tid];
    float w2v = w2[tid];
    float nd = fabsf(nu_diff[0]), na = fabsf(nu_adv[0]);
    for (int r = 0; r < 8; r++) {
        float h = tanhf(acc[r] + bb);
        red[tid] = h * w2v;
        __syncthreads();
        for (int s = 64; s > 0; s >>= 1) {
            if (tid < s) red[tid] += red[tid + s];
            __syncthreads();
        }
        if (tid == 0)
            g_nu[r0 + r] = nd + tanhf(red[0] + b2[0]) * na;
        __syncthreads();
    }
}

// ---------------- RoPE (in-place on Q,K; blended gate) ----------------
__global__ void rope_qk_kernel() {
    int idx = blockIdx.x * blockDim.x + threadIdx.x;
    if (idx >= CM * 512) return;
    int d = idx & 511;
    int row = idx >> 9;
    int t = row & (CL - 1);
    float g = g_gate[row];
    float cf, sf, c2, s2;
    rope_cs(g_invd[d], t, &cf, &sf);
    rope_cs(g_invd[512 + d], t, &c2, &s2);
    float c = g * cf + (1.f - g) * c2;
    float s = g * sf + (1.f - g) * s2;
    size_t lo = (size_t)row * CD + d, hi = lo + 512;
    float ql = g_Q[lo], qh = g_Q[hi];
    g_Q[lo] = ql * c - qh * s;
    g_Q[hi] = qh * c + ql * s;
    float kl = g_K[lo], kh = g_K[hi];
    g_K[lo] = kl * c - kh * s;
    g_K[hi] = kh * c + kl * s;
}

__global__ void rope_glu_kernel(const float* __restrict__ z) {
    int idx = blockIdx.x * blockDim.x + threadIdx.x;
    if (idx >= CM * 512) return;
    int d = idx & 511;
    int row = idx >> 9;
    int t = row & (CL - 1);
    float c, s;
    rope_cs(g_invd[1024 + d], t, &c, &s);
    size_t lo = (size_t)row * CD + d, hi = lo + 512;
    float xl = z[lo], xh = z[hi];
    g_zglu[lo] = xl * c - xh * s;
    g_zglu[hi] = xh * c + xl * s;
}

// ---------------- causal softmax (in-place on g_S rows) ----------------
__global__ __launch_bounds__(256) void softmax_kernel() {
    int gr = blockIdx.x;
    int l = gr & (CL - 1);
    float* row = g_S + (size_t)gr * CL;
    int n = l + 1;
    __shared__ float buf[CL];
    __shared__ float red[256];
    int tid = threadIdx.x;
    float mx = -3.4e38f;
    for (int i = tid; i < n; i += 256) { float v = row[i]; buf[i] = v; mx = fmaxf(mx, v); }
    red[tid] = mx; __syncthreads();
    for (int s = 128; s > 0; s >>= 1) {
        if (tid < s) red[tid] = fmaxf(red[tid], red[tid + s]);
        __syncthreads();
    }
    mx = red[0]; __syncthreads();
    float sum = 0.f;
    for (int i = tid; i < n; i += 256) { float e = expf(buf[i] - mx); buf[i] = e; sum += e; }
    red[tid] = sum; __syncthreads();
    for (int s = 128; s > 0; s >>= 1) {
        if (tid < s) red[tid] += red[tid + s];
        __syncthreads();
    }
    float rinv = 1.f / red[0];
    int bound = ((l >> 6) + 1) << 6;
    for (int i = tid; i < n; i += 256) row[i] = buf[i] * rinv;
    for (int i = n + tid; i < bound; i += 256) row[i] = 0.f;
}

// ---------------- attn_w = mean over heads ----------------
__global__ void awmean_kernel(float* __restrict__ aw) {
    size_t idx = (size_t)blockIdx.x * blockDim.x + threadIdx.x;
    const size_t tot = (size_t)CB * CL * CL;
    if (idx >= tot) return;
    size_t b = idx / ((size_t)CL * CL);
    size_t rem = idx - b * (size_t)CL * CL;
    int l = (int)(rem >> 11);
    int m = (int)(rem & (CL - 1));
    if (m > l) { aw[idx] = 0.f; return; }
    const float* p = g_S + b * (size_t)CNH * CL * CL + rem;
    float s = 0.f;
#pragma unroll
    for (int hh = 0; hh < CNH; hh++) s += p[(size_t)hh * CL * CL];
    aw[idx] = s * (1.f / CNH);
}

// ---------------- attn_out = probs @ V ----------------
__global__ __launch_bounds__(256) void attnout_kernel() {
    int l0 = blockIdx.x * 64;
    int h = blockIdx.y, b = blockIdx.z;
    const float* S = g_S + ((size_t)(b * CNH + h)) * CL * CL;
    const float* V = g_V + (size_t)b * CL * CD + h * CHD;
    float* O = g_ao + (size_t)b * CL * CD + h * CHD;
    __shared__ float Ps[64][68];
    __shared__ float Vs[64][68];
    int tid = threadIdx.x;
    int ty = tid >> 4, tx = tid & 15;
    int lr = tid >> 2, lc = (tid & 3) * 16;
    float acc[4][4];
#pragma unroll
    for (int i = 0; i < 4; i++)
#pragma unroll
        for (int j = 0; j < 4; j++) acc[i][j] = 0.f;

    for (int m0 = 0; m0 <= l0; m0 += 64) {
        const float* sp = S + (size_t)(l0 + lr) * CL + m0 + lc;
        float4 v0 = *(const float4*)sp;
        float4 v1 = *(const float4*)(sp + 4);
        float4 v2 = *(const float4*)(sp + 8);
        float4 v3 = *(const float4*)(sp + 12);
        *(float4*)&Ps[lr][lc]      = v0;
        *(float4*)&Ps[lr][lc + 4]  = v1;
        *(float4*)&Ps[lr][lc + 8]  = v2;
        *(float4*)&Ps[lr][lc + 12] = v3;
        const float* vp = V + (size_t)(m0 + lr) * CD + lc;
        float4 w0 = *(const float4*)vp;
        float4 w1 = *(const float4*)(vp + 4);
        float4 w2 = *(const float4*)(vp + 8);
        float4 w3 = *(const float4*)(vp + 12);
        *(float4*)&Vs[lr][lc]      = w0;
        *(float4*)&Vs[lr][lc + 4]  = w1;
        *(float4*)&Vs[lr][lc + 8]  = w2;
        *(float4*)&Vs[lr][lc + 12] = w3;
        __syncthreads();
#pragma unroll 8
        for (int k = 0; k < 64; k++) {
            float a0 = Ps[ty * 4 + 0][k];
            float a1 = Ps[ty * 4 + 1][k];
            float a2 = Ps[ty * 4 + 2][k];
            float a3 = Ps[ty * 4 + 3][k];
            float4 bv = *(const float4*)&Vs[k][tx * 4];
            acc[0][0] += a0 * bv.x; acc[0][1] += a0 * bv.y; acc[0][2] += a0 * bv.z; acc[0][3] += a0 * bv.w;
            acc[1][0] += a1 * bv.x; acc[1][1] += a1 * bv.y; acc[1][2] += a1 * bv.z; acc[1][3] += a1 * bv.w;
            acc[2][0] += a2 * bv.x; acc[2][1] += a2 * bv.y; acc[2][2] += a2 * bv.z; acc[2][3] += a2 * bv.w;
            acc[3][0] += a3 * bv.x; acc[3][1] += a3 * bv.y; acc[3][2] += a3 * bv.z; acc[3][3] += a3 * bv.w;
        }
        __syncthreads();
    }
#pragma unroll
    for (int i = 0; i < 4; i++)
#pragma unroll
        for (int j = 0; j < 4; j++)
            O[(size_t)(l0 + ty * 4 + i) * CD + tx * 4 + j] = acc[i][j];
}

// ---------------- bilinear * (-nu) + LayerNorm ----------------
__global__ __launch_bounds__(256) void bilin_ln_kernel(
    const float* __restrict__ ln_w, const float* __restrict__ ln_b)
{
    int row = blockIdx.x;
    int tid = threadIdx.x;
    size_t off = (size_t)row * CD;
    float nu = g_nu[row];
    __shared__ float red[256], red2[256];
    float a[4]; float s = 0.f, s2 = 0.f;
#pragma unroll
    for (int i = 0; i < 4; i++) {
        int d = tid + i * 256;
        float v = -nu * g_U[off + d] * g_Gg[off + d];
        a[i] = v; s += v; s2 += v * v;
    }
    red[tid] = s; red2[tid] = s2; __syncthreads();
    for (int st = 128; st > 0; st >>= 1) {
        if (tid < st) { red[tid] += red[tid + st]; red2[tid] += red2[tid + st]; }
        __syncthreads();
    }
    float mu = red[0] * (1.f / CD);
    float var = red2[0] * (1.f / CD) - mu * mu;
    float rstd = rsqrtf(var + 1e-5f);
#pragma unroll
    for (int i = 0; i < 4; i++) {
        int d = tid + i * 256;
        g_U[off + d] = (a[i] - mu) * rstd * ln_w[d] + ln_b[d];
    }
}

// ---------------- launcher ----------------
extern "C" void kernel_launch(void* const* d_in, const int* in_sizes, int n_in,
                              void* d_out, int out_size) {
    (void)in_sizes; (void)n_in; (void)out_size;
    const float* z     = (const float*)d_in[0];
    const float* Wq    = (const float*)d_in[1];
    const float* bq    = (const float*)d_in[2];
    const float* Wk    = (const float*)d_in[3];
    const float* bk    = (const float*)d_in[4];
    const float* Wv    = (const float*)d_in[5];
    const float* bv    = (const float*)d_in[6];
    const float* Wcoh  = (const float*)d_in[7];
    const float* gamma = (const float*)d_in[8];
    const float* rg_w1 = (const float*)d_in[9];
    const float* rg_b1 = (const float*)d_in[10];
    const float* rg_w2 = (const float*)d_in[11];
    const float* rg_b2 = (const float*)d_in[12];
    const float* nu_diff = (const float*)d_in[13];
    const float* nu_adv  = (const float*)d_in[14];
    const float* nu_w1 = (const float*)d_in[15];
    const float* nu_b1 = (const float*)d_in[16];
    const float* nu_w2 = (const float*)d_in[17];
    const float* nu_b2 = (const float*)d_in[18];
    const float* Wu    = (const float*)d_in[19];
    const float* bu    = (const float*)d_in[20];
    const float* Wg    = (const float*)d_in[21];
    const float* bg    = (const float*)d_in[22];
    const float* ln_w  = (const float*)d_in[23];
    const float* ln_b  = (const float*)d_in[24];
    const float* Cw    = (const float*)d_in[25];
    const float* Cb    = (const float*)d_in[26];

    float* out_z  = (float*)d_out;
    float* out_aw = out_z + (size_t)CM * CD;

    void* tmp;
    cudaGetSymbolAddress(&tmp, g_pool); float* pPool = (float*)tmp;
    cudaGetSymbolAddress(&tmp, g_Q);    float* pQ    = (float*)tmp;
    cudaGetSymbolAddress(&tmp, g_K);    float* pK    = (float*)tmp;
    cudaGetSymbolAddress(&tmp, g_V);    float* pV    = (float*)tmp;
    cudaGetSymbolAddress(&tmp, g_gk);   float* pGk   = (float*)tmp;
    cudaGetSymbolAddress(&tmp, g_zglu); float* pZg   = (float*)tmp;
    cudaGetSymbolAddress(&tmp, g_U);    float* pU    = (float*)tmp;
    cudaGetSymbolAddress(&tmp, g_Gg);   float* pG    = (float*)tmp;
    cudaGetSymbolAddress(&tmp, g_ao);   float* pAo   = (float*)tmp;
    cudaGetSymbolAddress(&tmp, g_gb);   float* pGb   = (float*)tmp;
    cudaGetSymbolAddress(&tmp, g_S);    float* pS    = (float*)tmp;
    (void)pV;

    const size_t SMEM = 2 * 9216 * sizeof(float);   // 73728
    cudaFuncSetAttribute(tc_gemm<0,0>, cudaFuncAttributeMaxDynamicSharedMemorySize, (int)SMEM);
    cudaFuncSetAttribute(tc_gemm<0,1>, cudaFuncAttributeMaxDynamicSharedMemorySize, (int)SMEM);
    cudaFuncSetAttribute(tc_gemm<1,2>, cudaFuncAttributeMaxDynamicSharedMemorySize, (int)SMEM);
    cudaFuncSetAttribute(tc_gemm<1,3>, cudaFuncAttributeMaxDynamicSharedMemorySize, (int)SMEM);

    dim3 gmain(CD / 128, CM / 128, 1);   // (8, 32)

    inv_kernel<<<1, 512>>>();
    pool_kernel<<<dim3(CD / 256, CB), 256>>>(z);

    tc_gemm<0,0><<<gmain, 256, SMEM>>>(z, Wq, bq, pQ, CD, CD, CD, CD,
        0,0,0,0,0,0,1, nullptr, nullptr, nullptr, nullptr);
    tc_gemm<0,0><<<gmain, 256, SMEM>>>(z, Wk, bk, pK, CD, CD, CD, CD,
        0,0,0,0,0,0,1, nullptr, nullptr, nullptr, nullptr);
    tc_gemm<0,0><<<gmain, 256, SMEM>>>(z, Wv, bv, pV, CD, CD, CD, CD,
        0,0,0,0,0,0,1, nullptr, nullptr, nullptr, nullptr);
    tc_gemm<0,0><<<gmain, 256, SMEM>>>(pPool, Wcoh, nullptr, pGk, CD, CD, CD, CD,
        0,0,0,0,0,0,1, nullptr, nullptr, nullptr, nullptr);

    gate_kernel<<<CM / 8, 256>>>(rg_w1, rg_b1, rg_w2, rg_b2);
    nu_kernel<<<CM / 8, 128>>>(nu_w1, nu_b1, nu_w2, nu_b2, nu_diff, nu_adv);

    // coherence bias: gb[b] = scale * gk[b] @ K_raw[b]^T  (pre-rope K)
    tc_gemm<1,2><<<dim3(CL/128, CL/128, CB), 256, SMEM>>>(pGk, pK, nullptr, pGb,
        CD, CD, CD, CL,
        (long)CL*CD, 0, (long)CL*CD, 0, (long)CL*CL, 0, 1,
        nullptr, nullptr, gamma, nullptr);

    rope_qk_kernel<<<(CM * 512) / 256, 256>>>();
    rope_glu_kernel<<<(CM * 512) / 256, 256>>>(z);

    tc_gemm<0,0><<<gmain, 256, SMEM>>>(pZg, Wu, bu, pU, CD, CD, CD, CD,
        0,0,0,0,0,0,1, nullptr, nullptr, nullptr, nullptr);
    tc_gemm<0,0><<<gmain, 256, SMEM>>>(pZg, Wg, bg, pG, CD, CD, CD, CD,
        0,0,0,0,0,0,1, nullptr, nullptr, nullptr, nullptr);

    // logits: S[b,h] = 0.125 * Qr_h @ Kr_h^T + gb[b], causal block skip
    tc_gemm<1,3><<<dim3(CL/128, CL/128, CB*CNH), 256, SMEM>>>(pQ, pK, nullptr, pS,
        CHD, CD, CD, CL,
        (long)CL*CD, CHD, (long)CL*CD, CHD, (long)CL*CL, (long)CL*CL, CNH,
        nullptr, nullptr, nullptr, pGb);

    softmax_kernel<<<CB * CNH * CL, 256>>>();
    awmean_kernel<<<(CB * CL * CL) / 256, 256>>>(out_aw);
    attnout_kernel<<<dim3(CL / 64, CNH, CB), 256>>>();

    bilin_ln_kernel<<<CM, 256>>>(ln_w, ln_b);
    tc_gemm<0,1><<<gmain, 256, SMEM>>>(pU, Cw, Cb, out_z, CD, CD, CD, CD,
        0,0,0,0,0,0,1, z, pAo, nullptr, nullptr);
}

// round 3
// speedup vs baseline: 1.9474x; 1.8894x over previous
#include <cuda_runtime.h>
#include <math.h>
#include <stdint.h>

#define CB 2
#define CL 2048
#define CD 1024
#define CNH 16
#define CHD 64
#define CM (CB*CL)          // 4096 rows
#define CHGATE 256
#define CHNU 128

// ---------------- scratch (device globals; allocation-free rule) ----------------
__device__ float g_pool[CM*CD];
__device__ float g_Q[CM*CD];
__device__ float g_K[CM*CD];
__device__ float g_V[CM*CD];
__device__ float g_gk[CM*CD];
__device__ float g_zglu[CM*CD];
__device__ float g_U[CM*CD];
__device__ float g_Gg[CM*CD];     // GLU gate branch
__device__ float g_ao[CM*CD];     // attention output
__device__ float g_zr[CM*CD];     // tf32-rounded z
__device__ float g_Wr[7*1048576]; // tf32-rounded weights
__device__ float g_gb[CB*CL*CL];  // coherence bias
__device__ float g_S[134217728];  // (B,NH,L,L) logits/probs
__device__ float g_gate[CM];
__device__ float g_nu[CM];
__device__ double g_invd[1536];   // inv freqs: [fast | slow | glu] x 512

// ---------------- tf32 helpers ----------------
__device__ __forceinline__ unsigned f2tf(float x) {
    unsigned r; asm("cvt.rna.tf32.f32 %0, %1;" : "=r"(r) : "f"(x)); return r;
}
__device__ __forceinline__ float tfr(float x) { return __uint_as_float(f2tf(x)); }
__device__ __forceinline__ void cpa16(float* s, const float* g) {
    unsigned sa = (unsigned)__cvta_generic_to_shared(s);
    asm volatile("cp.async.cg.shared.global [%0], [%1], 16;" :: "r"(sa), "l"(g));
}
__device__ __forceinline__ void mma8(float* d, const unsigned* a, const unsigned* b) {
    asm volatile(
        "mma.sync.aligned.m16n8k8.row.col.f32.tf32.tf32.f32 "
        "{%0,%1,%2,%3},{%4,%5,%6,%7},{%8,%9},{%0,%1,%2,%3};"
        : "+f"(d[0]), "+f"(d[1]), "+f"(d[2]), "+f"(d[3])
        : "r"(a[0]), "r"(a[1]), "r"(a[2]), "r"(a[3]), "r"(b[0]), "r"(b[1]));
}

__global__ void round_kernel(float* __restrict__ dst, const float* __restrict__ src, int n) {
    for (int i = blockIdx.x * blockDim.x + threadIdx.x; i < n; i += gridDim.x * blockDim.x)
        dst[i] = tfr(src[i]);
}

// ---------------- tensor-core GEMM: 128x128x32 tiles, tf32 (inputs pre-rounded) ----------------
// TB=0: C = A[M,K] @ B[K,N]      TB=1: C = A[M,K] @ B[N,K]^T
// MODE 0: C = acc + bias(optional); RND: round output to tf32
// MODE 1: C = r1 + 0.42*r2 + 1.07*(acc + bias)
// MODE 2: C = tanh(gamma)/32 * acc
// MODE 3: C = 0.125*acc + gb[l,m], causal blockskip
template<int TB, int MODE, int RND>
__global__ __launch_bounds__(256, 2) void tc_gemm(
    const float* __restrict__ A, const float* __restrict__ Bm,
    const float* __restrict__ bias, float* __restrict__ C,
    int K, int lda, int ldb, int ldc,
    long sAo, long sAi, long sBo, long sBi, long sCz, long sGo, int zdiv,
    const float* __restrict__ r1, const float* __restrict__ r2,
    const float* __restrict__ gamma, const float* __restrict__ gbb)
{
    const int bm = blockIdx.y * 128, bn = blockIdx.x * 128;
    if (MODE == 3 && bn >= bm + 128) return;
    const int z = blockIdx.z;
    const int zo = z / zdiv, zi = z - zo * zdiv;
    A  += (size_t)zo * sAo + (size_t)zi * sAi;
    Bm += (size_t)zo * sBo + (size_t)zi * sBi;
    C  += (size_t)z * sCz;
    const float* gbp = (MODE == 3) ? (gbb + (size_t)zo * sGo) : nullptr;

    extern __shared__ float sm[];
    const int STG = 9216;
    float* Asm[2] = { sm, sm + STG };
    float* Bsm[2] = { sm + 4608, sm + STG + 4608 };

    const int t = threadIdx.x;
    const int wid = t >> 5, lane = t & 31;
    const int wm = (wid >> 2) * 64, wn = (wid & 3) * 32;
    const int g = lane >> 2, tig = lane & 3;

    float acc[4][4][4];
#pragma unroll
    for (int i = 0; i < 4; i++)
#pragma unroll
        for (int j = 0; j < 4; j++)
#pragma unroll
            for (int q = 0; q < 4; q++) acc[i][j][q] = 0.f;

    auto loadA = [&](float* s, int k0) {
        int r = t >> 3, k4 = (t & 7) * 4;
#pragma unroll
        for (int it = 0; it < 4; it++)
            cpa16(s + (r + it*32)*36 + k4,
                  A + (size_t)(bm + r + it*32) * lda + k0 + k4);
    };
    auto loadB = [&](float* s, int k0) {
        if (TB == 0) {
            int k = t >> 5, n4 = (t & 31) * 4;
#pragma unroll
            for (int it = 0; it < 4; it++)
                cpa16(s + (k + it*8)*136 + n4,
                      Bm + (size_t)(k0 + k + it*8) * ldb + bn + n4);
        } else {
            int r = t >> 3, k4 = (t & 7) * 4;
#pragma unroll
            for (int it = 0; it < 4; it++)
                cpa16(s + (r + it*32)*36 + k4,
                      Bm + (size_t)(bn + r + it*32) * ldb + k0 + k4);
        }
    };

    const int NT = K >> 5;
    loadA(Asm[0], 0); loadB(Bsm[0], 0);
    asm volatile("cp.async.commit_group;");

    for (int kt = 0; kt < NT; kt++) {
        if (kt + 1 < NT) {
            loadA(Asm[(kt+1)&1], (kt+1)*32);
            loadB(Bsm[(kt+1)&1], (kt+1)*32);
            asm volatile("cp.async.commit_group;");
            asm volatile("cp.async.wait_group 1;");
        } else {
            asm volatile("cp.async.wait_group 0;");
        }
        __syncthreads();
        const unsigned* Ab = (const unsigned*)Asm[kt&1];
        const unsigned* Bb = (const unsigned*)Bsm[kt&1];
#pragma unroll
        for (int ks = 0; ks < 4; ks++) {
            const int k = ks * 8;
            unsigned af[4][4];
#pragma unroll
            for (int i = 0; i < 4; i++) {
                const unsigned* ap = Ab + (wm + 16*i + g)*36 + k + tig;
                af[i][0] = ap[0];
                af[i][1] = ap[8*36];
                af[i][2] = ap[4];
                af[i][3] = ap[8*36 + 4];
            }
            unsigned bf[4][2];
#pragma unroll
            for (int j = 0; j < 4; j++) {
                if (TB == 0) {
                    const unsigned* bp = Bb + (k + tig)*136 + wn + 8*j + g;
                    bf[j][0] = bp[0];
                    bf[j][1] = bp[4*136];
                } else {
                    const unsigned* bp = Bb + (wn + 8*j + g)*36 + k + tig;
                    bf[j][0] = bp[0];
                    bf[j][1] = bp[4];
                }
            }
#pragma unroll
            for (int i = 0; i < 4; i++)
#pragma unroll
                for (int j = 0; j < 4; j++)
                    mma8(acc[i][j], af[i], bf[j]);
        }
        __syncthreads();
    }

    float scale = 1.f;
    if (MODE == 2) scale = tanhf(gamma[0]) * 0.03125f;
    if (MODE == 3) scale = 0.125f;
#pragma unroll
    for (int i = 0; i < 4; i++) {
        const int r0 = bm + wm + 16*i + g;
#pragma unroll
        for (int j = 0; j < 4; j++) {
            const int c0 = bn + wn + 8*j + 2*tig;
#pragma unroll
            for (int h2 = 0; h2 < 2; h2++) {
                const int rr = r0 + h2*8;
                float v0 = acc[i][j][h2*2], v1 = acc[i][j][h2*2+1];
                const size_t off = (size_t)rr * ldc + c0;
                if (MODE == 0) {
                    if (bias) { v0 += bias[c0]; v1 += bias[c0+1]; }
                    if (RND) { v0 = tfr(v0); v1 = tfr(v1); }
                    C[off] = v0; C[off+1] = v1;
                } else if (MODE == 1) {
                    C[off]   = r1[off]   + 0.42f*r2[off]   + 1.07f*(v0 + bias[c0]);
                    C[off+1] = r1[off+1] + 0.42f*r2[off+1] + 1.07f*(v1 + bias[c0+1]);
                } else if (MODE == 2) {
                    C[off] = tfr(v0*scale); C[off+1] = tfr(v1*scale);
                } else {
                    const size_t go = (size_t)rr * CL + c0;
                    C[off]   = v0*scale + gbp[go];
                    C[off+1] = v1*scale + gbp[go+1];
                }
            }
        }
    }
}

// ---------------- attn_out = P @ V on tensor cores (per head, causal) ----------------
__global__ __launch_bounds__(256, 2) void attn_pv() {
    const int l0 = blockIdx.x * 128;
    const int h = blockIdx.y, b = blockIdx.z;
    const float* S = g_S + ((size_t)(b * CNH + h)) * CL * CL;
    const float* V = g_V + (size_t)b * CL * CD + h * CHD;
    float* O = g_ao + (size_t)b * CL * CD + h * CHD;

    extern __shared__ float sm[];
    const int STG = 4608 + 2304;              // S tile 128x36 + V tile 32x72
    float* Ssm[2] = { sm, sm + STG };
    float* Vsm[2] = { sm + 4608, sm + STG + 4608 };

    const int t = threadIdx.x;
    const int wid = t >> 5, lane = t & 31;
    const int wm = wid * 16;
    const int g = lane >> 2, tig = lane & 3;

    float acc[8][4];
#pragma unroll
    for (int j = 0; j < 8; j++)
#pragma unroll
        for (int q = 0; q < 4; q++) acc[j][q] = 0.f;

    auto loadS = [&](float* s, int k0) {
        int r = t >> 3, k4 = (t & 7) * 4;
#pragma unroll
        for (int it = 0; it < 4; it++)
            cpa16(s + (r + it*32)*36 + k4,
                  S + (size_t)(l0 + r + it*32) * CL + k0 + k4);
    };
    auto loadV = [&](float* s, int k0) {
        int kr = t >> 4, n4 = (t & 15) * 4;
#pragma unroll
        for (int it = 0; it < 2; it++)
            cpa16(s + (kr + it*16)*72 + n4,
                  V + (size_t)(k0 + kr + it*16) * CD + n4);
    };

    const int NT = (l0 + 128) >> 5;
    loadS(Ssm[0], 0); loadV(Vsm[0], 0);
    asm volatile("cp.async.commit_group;");

    for (int kt = 0; kt < NT; kt++) {
        if (kt + 1 < NT) {
            loadS(Ssm[(kt+1)&1], (kt+1)*32);
            loadV(Vsm[(kt+1)&1], (kt+1)*32);
            asm volatile("cp.async.commit_group;");
            asm volatile("cp.async.wait_group 1;");
        } else {
            asm volatile("cp.async.wait_group 0;");
        }
        __syncthreads();
        const unsigned* Ab = (const unsigned*)Ssm[kt&1];
        const unsigned* Bb = (const unsigned*)Vsm[kt&1];
#pragma unroll
        for (int ks = 0; ks < 4; ks++) {
            const int k = ks * 8;
            unsigned af[4];
            const unsigned* ap = Ab + (wm + g)*36 + k + tig;
            af[0] = ap[0];
            af[1] = ap[8*36];
            af[2] = ap[4];
            af[3] = ap[8*36 + 4];
            unsigned bf[8][2];
#pragma unroll
            for (int j = 0; j < 8; j++) {
                const unsigned* bp = Bb + (k + tig)*72 + 8*j + g;
                bf[j][0] = bp[0];
                bf[j][1] = bp[4*72];
            }
#pragma unroll
            for (int j = 0; j < 8; j++)
                mma8(acc[j], af, bf[j]);
        }
        __syncthreads();
    }
#pragma unroll
    for (int j = 0; j < 8; j++) {
        const int c0 = 8*j + 2*tig;
#pragma unroll
        for (int h2 = 0; h2 < 2; h2++) {
            const int rr = l0 + wm + g + h2*8;
            O[(size_t)rr * CD + c0]     = acc[j][h2*2];
            O[(size_t)rr * CD + c0 + 1] = acc[j][h2*2 + 1];
        }
    }
}

// ---------------- rope helpers ----------------
__global__ void inv_kernel() {
    int d = threadIdx.x;
    double e = (double)(2 * d) / (double)CD;
    g_invd[d]        = pow(1.6180339887498948482, -e);
    g_invd[512 + d]  = pow(1618.0, -e);
    g_invd[1024 + d] = pow(16180.0, -e);
}

__device__ __forceinline__ void rope_cs(double inv, int t, float* c, float* s) {
    double ang = (double)t * inv;
    double k = floor(ang * 0.15915494309189533576888376337251436);
    float a = (float)(ang - k * 6.28318530717958647692528676655900577);
    sincosf(a, s, c);
}

// ---------------- causal cumulative mean (tf32-rounded out) ----------------
__global__ void pool_kernel(const float* __restrict__ z) {
    int d = blockIdx.x * blockDim.x + threadIdx.x;
    int b = blockIdx.y;
    const float* zp = z + (size_t)b * CL * CD + d;
    float* pp = g_pool + (size_t)b * CL * CD + d;
    float acc = 0.f;
    for (int l = 0; l < CL; l++) {
        acc += zp[(size_t)l * CD];
        pp[(size_t)l * CD] = tfr(acc / (float)(l + 1));
    }
}

// ---------------- gate MLP (H=256) ----------------
__global__ __launch_bounds__(256) void gate_kernel(
    const float* __restrict__ w1, const float* __restrict__ b1,
    const float* __restrict__ w2, const float* __restrict__ b2)
{
    __shared__ float ps[8][1024];
    __shared__ float red[256];
    const int tid = threadIdx.x;
    const int r0 = blockIdx.x * 8;
    for (int i = tid; i < 8 * 1024; i += 256)
        ps[i >> 10][i & 1023] = g_pool[(size_t)r0 * CD + i];
    __syncthreads();
    float acc[8];
#pragma unroll
    for (int r = 0; r < 8; r++) acc[r] = 0.f;
    for (int k = 0; k < CD; k++) {
        float w = w1[(size_t)k * CHGATE + tid];
#pragma unroll
        for (int r = 0; r < 8; r++) acc[r] = fmaf(ps[r][k], w, acc[r]);
    }
    float bb = b1[tid];
    float w2v = w2[tid];
    for (int r = 0; r < 8; r++) {
        float x = acc[r] + bb;
        float h = 0.5f * x * (1.f + erff(x * 0.7071067811865476f));
        red[tid] = h * w2v;
        __syncthreads();
        for (int s = 128; s > 0; s >>= 1) {
            if (tid < s) red[tid] += red[tid + s];
            __syncthreads();
        }
        if (tid == 0) {
            float y = red[0] + b2[0];
            g_gate[r0 + r] = 1.f / (1.f + expf(-y));
        }
        __syncthreads();
    }
}

// ---------------- viscosity MLP (H=128) ----------------
__global__ __launch_bounds__(128) void nu_kernel(
    const float* __restrict__ w1, const float* __restrict__ b1,
    const float* __restrict__ w2, const float* __restrict__ b2,
    const float* __restrict__ nu_diff, const float* __restrict__ nu_adv)
{
    __shared__ float ps[8][1024];
    __shared__ float red[128];
    const int tid = threadIdx.x;
    const int r0 = blockIdx.x * 8;
    for (int i = tid; i < 8 * 1024; i += 128)
        ps[i >> 10][i & 1023] = g_pool[(size_t)r0 * CD + i];
    __syncthreads();
    float acc[8];
#pragma unroll
    for (int r = 0; r < 8; r++) acc[r] = 0.f;
    for (int k = 0; k < CD; k++) {
        float w = w1[(size_t)k * CHNU + tid];
#pragma unroll
        for (int r = 0; r < 8; r++) acc[r] = fmaf(ps[r][k], w, acc[r]);
    }
    float bb = b1[tid];
    float w2v = w2[tid];
    float nd = fabsf(nu_diff[0]), na = fabsf(nu_adv[0]);
    for (int r = 0; r < 8; r++) {
        float h = tanhf(acc[r] + bb);
        red[tid] = h * w2v;
        __syncthreads();
        for (int s = 64; s > 0; s >>= 1) {
            if (tid < s) red[tid] += red[tid + s];
            __syncthreads();
        }
        if (tid == 0)
            g_nu[r0 + r] = nd + tanhf(red[0] + b2[0]) * na;
        __syncthreads();
    }
}

// ---------------- RoPE (in-place on Q,K; blended gate; rounded out) ----------------
__global__ void rope_qk_kernel() {
    int idx = blockIdx.x * blockDim.x + threadIdx.x;
    if (idx >= CM * 512) return;
    int d = idx & 511;
    int row = idx >> 9;
    int t = row & (CL - 1);
    float g = g_gate[row];
    float cf, sf, c2, s2;
    rope_cs(g_invd[d], t, &cf, &sf);
    rope_cs(g_invd[512 + d], t, &c2, &s2);
    float c = g * cf + (1.f - g) * c2;
    float s = g * sf + (1.f - g) * s2;
    size_t lo = (size_t)row * CD + d, hi = lo + 512;
    float ql = g_Q[lo], qh = g_Q[hi];
    g_Q[lo] = tfr(ql * c - qh * s);
    g_Q[hi] = tfr(qh * c + ql * s);
    float kl = g_K[lo], kh = g_K[hi];
    g_K[lo] = tfr(kl * c - kh * s);
    g_K[hi] = tfr(kh * c + kl * s);
}

__global__ void rope_glu_kernel(const float* __restrict__ z) {
    int idx = blockIdx.x * blockDim.x + threadIdx.x;
    if (idx >= CM * 512) return;
    int d = idx & 511;
    int row = idx >> 9;
    int t = row & (CL - 1);
    float c, s;
    rope_cs(g_invd[1024 + d], t, &c, &s);
    size_t lo = (size_t)row * CD + d, hi = lo + 512;
    float xl = z[lo], xh = z[hi];
    g_zglu[lo] = tfr(xl * c - xh * s);
    g_zglu[hi] = tfr(xh * c + xl * s);
}

// ---------------- fused causal softmax (16 heads) + head-mean ----------------
__global__ __launch_bounds__(256) void smaw_kernel(float* __restrict__ aw) {
    const int l = blockIdx.x;
    const int b = blockIdx.y;
    const int n = l + 1;
    const int bound = ((l >> 7) + 1) << 7;     // 128-block boundary for attn_pv
    const int tid = threadIdx.x;
    const int lane = tid & 31, wid = tid >> 5;
    __shared__ float red[8];
    float awacc[8];
#pragma unroll
    for (int ii = 0; ii < 8; ii++) awacc[ii] = 0.f;

    for (int h = 0; h < CNH; h++) {
        float* row = g_S + ((size_t)(b * CNH + h) * CL + l) * CL;
        float vals[8];
        float mx = -3.4e38f;
#pragma unroll
        for (int ii = 0; ii < 8; ii++) {
            int col = tid + ii * 256;
            vals[ii] = (col < n) ? row[col] : -3.4e38f;
            mx = fmaxf(mx, vals[ii]);
        }
#pragma unroll
        for (int o = 16; o > 0; o >>= 1) mx = fmaxf(mx, __shfl_xor_sync(~0u, mx, o));
        if (lane == 0) red[wid] = mx;
        __syncthreads();
        mx = red[0];
#pragma unroll
        for (int w = 1; w < 8; w++) mx = fmaxf(mx, red[w]);
        __syncthreads();

        float sum = 0.f;
#pragma unroll
        for (int ii = 0; ii < 8; ii++) {
            int col = tid + ii * 256;
            float e = (col < n) ? expf(vals[ii] - mx) : 0.f;
            vals[ii] = e;
            sum += e;
        }
#pragma unroll
        for (int o = 16; o > 0; o >>= 1) sum += __shfl_xor_sync(~0u, sum, o);
        if (lane == 0) red[wid] = sum;
        __syncthreads();
        sum = red[0];
#pragma unroll
        for (int w = 1; w < 8; w++) sum += red[w];
        __syncthreads();
        float rinv = 1.f / sum;

#pragma unroll
        for (int ii = 0; ii < 8; ii++) {
            int col = tid + ii * 256;
            if (col < n) {
                float p = vals[ii] * rinv;
                row[col] = tfr(p);
                awacc[ii] += p;
            } else if (col < bound) {
                row[col] = 0.f;
            }
        }
    }
    float* awr = aw + ((size_t)b * CL + l) * CL;
#pragma unroll
    for (int ii = 0; ii < 8; ii++) {
        int col = tid + ii * 256;
        awr[col] = (col < n) ? awacc[ii] * (1.f / CNH) : 0.f;
    }
}

// ---------------- bilinear * (-nu) + LayerNorm (rounded out) ----------------
__global__ __launch_bounds__(256) void bilin_ln_kernel(
    const float* __restrict__ ln_w, const float* __restrict__ ln_b)
{
    int row = blockIdx.x;
    int tid = threadIdx.x;
    size_t off = (size_t)row * CD;
    float nu = g_nu[row];
    __shared__ float red[256], red2[256];
    float a[4]; float s = 0.f, s2 = 0.f;
#pragma unroll
    for (int i = 0; i < 4; i++) {
        int d = tid + i * 256;
        float v = -nu * g_U[off + d] * g_Gg[off + d];
        a[i] = v; s += v; s2 += v * v;
    }
    red[tid] = s; red2[tid] = s2; __syncthreads();
    for (int st = 128; st > 0; st >>= 1) {
        if (tid < st) { red[tid] += red[tid + st]; red2[tid] += red2[tid + st]; }
        __syncthreads();
    }
    float mu = red[0] * (1.f / CD);
    float var = red2[0] * (1.f / CD) - mu * mu;
    float rstd = rsqrtf(var + 1e-5f);
#pragma unroll
    for (int i = 0; i < 4; i++) {
        int d = tid + i * 256;
        g_U[off + d] = tfr((a[i] - mu) * rstd * ln_w[d] + ln_b[d]);
    }
}

// ---------------- launcher ----------------
extern "C" void kernel_launch(void* const* d_in, const int* in_sizes, int n_in,
                              void* d_out, int out_size) {
    (void)in_sizes; (void)n_in; (void)out_size;
    const float* z     = (const float*)d_in[0];
    const float* Wq    = (const float*)d_in[1];
    const float* bq    = (const float*)d_in[2];
    const float* Wk    = (const float*)d_in[3];
    const float* bk    = (const float*)d_in[4];
    const float* Wv    = (const float*)d_in[5];
    const float* bv    = (const float*)d_in[6];
    const float* Wcoh  = (const float*)d_in[7];
    const float* gamma = (const float*)d_in[8];
    const float* rg_w1 = (const float*)d_in[9];
    const float* rg_b1 = (const float*)d_in[10];
    const float* rg_w2 = (const float*)d_in[11];
    const float* rg_b2 = (const float*)d_in[12];
    const float* nu_diff = (const float*)d_in[13];
    const float* nu_adv  = (const float*)d_in[14];
    const float* nu_w1 = (const float*)d_in[15];
    const float* nu_b1 = (const float*)d_in[16];
    const float* nu_w2 = (const float*)d_in[17];
    const float* nu_b2 = (const float*)d_in[18];
    const float* Wu    = (const float*)d_in[19];
    const float* bu    = (const float*)d_in[20];
    const float* Wg    = (const float*)d_in[21];
    const float* bg    = (const float*)d_in[22];
    const float* ln_w  = (const float*)d_in[23];
    const float* ln_b  = (const float*)d_in[24];
    const float* Cw    = (const float*)d_in[25];
    const float* Cb    = (const float*)d_in[26];

    float* out_z  = (float*)d_out;
    float* out_aw = out_z + (size_t)CM * CD;

    void* tmp;
    cudaGetSymbolAddress(&tmp, g_pool); float* pPool = (float*)tmp;
    cudaGetSymbolAddress(&tmp, g_Q);    float* pQ    = (float*)tmp;
    cudaGetSymbolAddress(&tmp, g_K);    float* pK    = (float*)tmp;
    cudaGetSymbolAddress(&tmp, g_V);    float* pV    = (float*)tmp;
    cudaGetSymbolAddress(&tmp, g_gk);   float* pGk   = (float*)tmp;
    cudaGetSymbolAddress(&tmp, g_zglu); float* pZg   = (float*)tmp;
    cudaGetSymbolAddress(&tmp, g_U);    float* pU    = (float*)tmp;
    cudaGetSymbolAddress(&tmp, g_Gg);   float* pG    = (float*)tmp;
    cudaGetSymbolAddress(&tmp, g_ao);   float* pAo   = (float*)tmp;
    cudaGetSymbolAddress(&tmp, g_zr);   float* pZr   = (float*)tmp;
    cudaGetSymbolAddress(&tmp, g_Wr);   float* pWr   = (float*)tmp;
    cudaGetSymbolAddress(&tmp, g_gb);   float* pGb   = (float*)tmp;
    cudaGetSymbolAddress(&tmp, g_S);    float* pS    = (float*)tmp;

    float* rWq = pWr;
    float* rWk = pWr + 1048576;
    float* rWv = pWr + 2*1048576;
    float* rWc = pWr + 3*1048576;
    float* rWu = pWr + 4*1048576;
    float* rWg = pWr + 5*1048576;
    float* rCw = pWr + 6*1048576;

    const size_t SMEM  = 2 * 9216 * sizeof(float);   // 73728
    const size_t SMEMP = 2 * 6912 * sizeof(float);   // 55296 (attn_pv)
    cudaFuncSetAttribute(tc_gemm<0,0,0>, cudaFuncAttributeMaxDynamicSharedMemorySize, (int)SMEM);
    cudaFuncSetAttribute(tc_gemm<0,0,1>, cudaFuncAttributeMaxDynamicSharedMemorySize, (int)SMEM);
    cudaFuncSetAttribute(tc_gemm<0,1,0>, cudaFuncAttributeMaxDynamicSharedMemorySize, (int)SMEM);
    cudaFuncSetAttribute(tc_gemm<1,2,0>, cudaFuncAttributeMaxDynamicSharedMemorySize, (int)SMEM);
    cudaFuncSetAttribute(tc_gemm<1,3,0>, cudaFuncAttributeMaxDynamicSharedMemorySize, (int)SMEM);
    cudaFuncSetAttribute(attn_pv, cudaFuncAttributeMaxDynamicSharedMemorySize, (int)SMEMP);

    dim3 gmain(CD / 128, CM / 128, 1);   // (8, 32)

    inv_kernel<<<1, 512>>>();
    round_kernel<<<1024, 256>>>(rWq, Wq, 1048576);
    round_kernel<<<1024, 256>>>(rWk, Wk, 1048576);
    round_kernel<<<1024, 256>>>(rWv, Wv, 1048576);
    round_kernel<<<1024, 256>>>(rWc, Wcoh, 1048576);
    round_kernel<<<1024, 256>>>(rWu, Wu, 1048576);
    round_kernel<<<1024, 256>>>(rWg, Wg, 1048576);
    round_kernel<<<1024, 256>>>(rCw, Cw, 1048576);
    round_kernel<<<2048, 256>>>(pZr, z, CM*CD);
    pool_kernel<<<dim3(CD / 256, CB), 256>>>(z);

    tc_gemm<0,0,0><<<gmain, 256, SMEM>>>(pZr, rWq, bq, pQ, CD, CD, CD, CD,
        0,0,0,0,0,0,1, nullptr, nullptr, nullptr, nullptr);
    tc_gemm<0,0,1><<<gmain, 256, SMEM>>>(pZr, rWk, bk, pK, CD, CD, CD, CD,
        0,0,0,0,0,0,1, nullptr, nullptr, nullptr, nullptr);
    tc_gemm<0,0,1><<<gmain, 256, SMEM>>>(pZr, rWv, bv, pV, CD, CD, CD, CD,
        0,0,0,0,0,0,1, nullptr, nullptr, nullptr, nullptr);
    tc_gemm<0,0,1><<<gmain, 256, SMEM>>>(pPool, rWc, nullptr, pGk, CD, CD, CD, CD,
        0,0,0,0,0,0,1, nullptr, nullptr, nullptr, nullptr);

    gate_kernel<<<CM / 8, 256>>>(rg_w1, rg_b1, rg_w2, rg_b2);
    nu_kernel<<<CM / 8, 128>>>(nu_w1, nu_b1, nu_w2, nu_b2, nu_diff, nu_adv);

    tc_gemm<1,2,0><<<dim3(CL/128, CL/128, CB), 256, SMEM>>>(pGk, pK, nullptr, pGb,
        CD, CD, CD, CL,
        (long)CL*CD, 0, (long)CL*CD, 0, (long)CL*CL, 0, 1,
        nullptr, nullptr, gamma, nullptr);

    rope_qk_kernel<<<(CM * 512) / 256, 256>>>();
    rope_glu_kernel<<<(CM * 512) / 256, 256>>>(z);

    tc_gemm<0,0,0><<<gmain, 256, SMEM>>>(pZg, rWu, bu, pU, CD, CD, CD, CD,
        0,0,0,0,0,0,1, nullptr, nullptr, nullptr, nullptr);
    tc_gemm<0,0,0><<<gmain, 256, SMEM>>>(pZg, rWg, bg, pG, CD, CD, CD, CD,
        0,0,0,0,0,0,1, nullptr, nullptr, nullptr, nullptr);

    tc_gemm<1,3,0><<<dim3(CL/128, CL/128, CB*CNH), 256, SMEM>>>(pQ, pK, nullptr, pS,
        CHD, CD, CD, CL,
        (long)CL*CD, CHD, (long)CL*CD, CHD, (long)CL*CL, (long)CL*CL, CNH,
        nullptr, nullptr, nullptr, pGb);

    smaw_kernel<<<dim3(CL, CB), 256>>>(out_aw);
    attn_pv<<<dim3(CL/128, CNH, CB), 256, SMEMP>>>();

    bilin_ln_kernel<<<CM, 256>>>(ln_w, ln_b);
    tc_gemm<0,1,0><<<gmain, 256, SMEM>>>(pU, rCw, Cb, out_z, CD, CD, CD, CD,
        0,0,0,0,0,0,1, z, pAo, nullptr, nullptr);
}

// round 4
// speedup vs baseline: 2.7615x; 1.4180x over previous
#include <cuda_runtime.h>
#include <math.h>
#include <stdint.h>

#define CB 2
#define CL 2048
#define CD 1024
#define CNH 16
#define CHD 64
#define CM (CB*CL)          // 4096 rows
#define CHGATE 256
#define CHNU 128

// ---------------- scratch (device globals; allocation-free rule) ----------------
__device__ float g_pool[CM*CD];
__device__ float g_Q[CM*CD];
__device__ float g_K[CM*CD];
__device__ float g_V[CM*CD];
__device__ float g_gk[CM*CD];
__device__ float g_zglu[CM*CD];
__device__ float g_U[CM*CD];
__device__ float g_Gg[CM*CD];     // GLU gate branch
__device__ float g_ao[CM*CD];     // attention output
__device__ float g_zr[CM*CD];     // tf32-rounded z
__device__ float g_Wr[7*1048576 + 393216]; // tf32-rounded weights (+rg_w1,nu_w1)
__device__ float g_gb[CB*CL*CL];  // coherence bias
__device__ float g_S[134217728];  // (B,NH,L,L) logits/probs (also MLP hidden scratch)
__device__ float g_gate[CM];
__device__ float g_nu[CM];
__device__ float g_csum[CB*32*CD];// pool chunk sums
__device__ double g_invd[1536];   // inv freqs: [fast | slow | glu] x 512

// ---------------- tf32 helpers ----------------
__device__ __forceinline__ unsigned f2tf(float x) {
    unsigned r; asm("cvt.rna.tf32.f32 %0, %1;" : "=r"(r) : "f"(x)); return r;
}
__device__ __forceinline__ float tfr(float x) { return __uint_as_float(f2tf(x)); }
__device__ __forceinline__ void cpa16(float* s, const float* g) {
    unsigned sa = (unsigned)__cvta_generic_to_shared(s);
    asm volatile("cp.async.cg.shared.global [%0], [%1], 16;" :: "r"(sa), "l"(g));
}
__device__ __forceinline__ void mma8(float* d, const unsigned* a, const unsigned* b) {
    asm volatile(
        "mma.sync.aligned.m16n8k8.row.col.f32.tf32.tf32.f32 "
        "{%0,%1,%2,%3},{%4,%5,%6,%7},{%8,%9},{%0,%1,%2,%3};"
        : "+f"(d[0]), "+f"(d[1]), "+f"(d[2]), "+f"(d[3])
        : "r"(a[0]), "r"(a[1]), "r"(a[2]), "r"(a[3]), "r"(b[0]), "r"(b[1]));
}

// ---------------- merged tf32 rounding pass ----------------
struct RndArgs { const float* src[9]; float* dst[9]; int n[9]; };
__global__ void roundN_kernel(RndArgs a) {
    int r = blockIdx.y;
    const float* s = a.src[r];
    float* d = a.dst[r];
    int n = a.n[r];
    for (int i = blockIdx.x * blockDim.x + threadIdx.x; i < n; i += gridDim.x * blockDim.x)
        d[i] = tfr(s[i]);
}

// ---------------- tensor-core GEMM: 128x128x32 tiles, tf32 (inputs pre-rounded) ----------------
// TB=0: C = A[M,K] @ B[K,N]      TB=1: C = A[M,K] @ B[N,K]^T
// MODE 0: C = acc + bias(optional); RND: round output to tf32
// MODE 1: C = r1 + 0.42*r2 + 1.07*(acc + bias)
// MODE 2: C = tanh(gamma)/32 * acc
// MODE 3: C = 0.125*acc + gb[l,m], causal blockskip
template<int TB, int MODE, int RND>
__global__ __launch_bounds__(256, 2) void tc_gemm(
    const float* __restrict__ A, const float* __restrict__ Bm,
    const float* __restrict__ bias, float* __restrict__ C,
    int K, int lda, int ldb, int ldc,
    long sAo, long sAi, long sBo, long sBi, long sCz, long sGo, int zdiv,
    const float* __restrict__ r1, const float* __restrict__ r2,
    const float* __restrict__ gamma, const float* __restrict__ gbb)
{
    const int bm = blockIdx.y * 128, bn = blockIdx.x * 128;
    if (MODE == 3 && bn >= bm + 128) return;
    const int z = blockIdx.z;
    const int zo = z / zdiv, zi = z - zo * zdiv;
    A  += (size_t)zo * sAo + (size_t)zi * sAi;
    Bm += (size_t)zo * sBo + (size_t)zi * sBi;
    C  += (size_t)z * sCz;
    const float* gbp = (MODE == 3) ? (gbb + (size_t)zo * sGo) : nullptr;

    extern __shared__ float sm[];
    const int STG = 9216;
    float* Asm[2] = { sm, sm + STG };
    float* Bsm[2] = { sm + 4608, sm + STG + 4608 };

    const int t = threadIdx.x;
    const int wid = t >> 5, lane = t & 31;
    const int wm = (wid >> 2) * 64, wn = (wid & 3) * 32;
    const int g = lane >> 2, tig = lane & 3;

    float acc[4][4][4];
#pragma unroll
    for (int i = 0; i < 4; i++)
#pragma unroll
        for (int j = 0; j < 4; j++)
#pragma unroll
            for (int q = 0; q < 4; q++) acc[i][j][q] = 0.f;

    auto loadA = [&](float* s, int k0) {
        int r = t >> 3, k4 = (t & 7) * 4;
#pragma unroll
        for (int it = 0; it < 4; it++)
            cpa16(s + (r + it*32)*36 + k4,
                  A + (size_t)(bm + r + it*32) * lda + k0 + k4);
    };
    auto loadB = [&](float* s, int k0) {
        if (TB == 0) {
            int k = t >> 5, n4 = (t & 31) * 4;
#pragma unroll
            for (int it = 0; it < 4; it++)
                cpa16(s + (k + it*8)*136 + n4,
                      Bm + (size_t)(k0 + k + it*8) * ldb + bn + n4);
        } else {
            int r = t >> 3, k4 = (t & 7) * 4;
#pragma unroll
            for (int it = 0; it < 4; it++)
                cpa16(s + (r + it*32)*36 + k4,
                      Bm + (size_t)(bn + r + it*32) * ldb + k0 + k4);
        }
    };

    const int NT = K >> 5;
    loadA(Asm[0], 0); loadB(Bsm[0], 0);
    asm volatile("cp.async.commit_group;");

    for (int kt = 0; kt < NT; kt++) {
        if (kt + 1 < NT) {
            loadA(Asm[(kt+1)&1], (kt+1)*32);
            loadB(Bsm[(kt+1)&1], (kt+1)*32);
            asm volatile("cp.async.commit_group;");
            asm volatile("cp.async.wait_group 1;");
        } else {
            asm volatile("cp.async.wait_group 0;");
        }
        __syncthreads();
        const unsigned* Ab = (const unsigned*)Asm[kt&1];
        const unsigned* Bb = (const unsigned*)Bsm[kt&1];
#pragma unroll
        for (int ks = 0; ks < 4; ks++) {
            const int k = ks * 8;
            unsigned af[4][4];
#pragma unroll
            for (int i = 0; i < 4; i++) {
                const unsigned* ap = Ab + (wm + 16*i + g)*36 + k + tig;
                af[i][0] = ap[0];
                af[i][1] = ap[8*36];
                af[i][2] = ap[4];
                af[i][3] = ap[8*36 + 4];
            }
            unsigned bf[4][2];
#pragma unroll
            for (int j = 0; j < 4; j++) {
                if (TB == 0) {
                    const unsigned* bp = Bb + (k + tig)*136 + wn + 8*j + g;
                    bf[j][0] = bp[0];
                    bf[j][1] = bp[4*136];
                } else {
                    const unsigned* bp = Bb + (wn + 8*j + g)*36 + k + tig;
                    bf[j][0] = bp[0];
                    bf[j][1] = bp[4];
                }
            }
#pragma unroll
            for (int i = 0; i < 4; i++)
#pragma unroll
                for (int j = 0; j < 4; j++)
                    mma8(acc[i][j], af[i], bf[j]);
        }
        __syncthreads();
    }

    float scale = 1.f;
    if (MODE == 2) scale = tanhf(gamma[0]) * 0.03125f;
    if (MODE == 3) scale = 0.125f;
#pragma unroll
    for (int i = 0; i < 4; i++) {
        const int r0 = bm + wm + 16*i + g;
#pragma unroll
        for (int j = 0; j < 4; j++) {
            const int c0 = bn + wn + 8*j + 2*tig;
#pragma unroll
            for (int h2 = 0; h2 < 2; h2++) {
                const int rr = r0 + h2*8;
                float v0 = acc[i][j][h2*2], v1 = acc[i][j][h2*2+1];
                const size_t off = (size_t)rr * ldc + c0;
                if (MODE == 0) {
                    if (bias) { v0 += bias[c0]; v1 += bias[c0+1]; }
                    if (RND) { v0 = tfr(v0); v1 = tfr(v1); }
                    C[off] = v0; C[off+1] = v1;
                } else if (MODE == 1) {
                    C[off]   = r1[off]   + 0.42f*r2[off]   + 1.07f*(v0 + bias[c0]);
                    C[off+1] = r1[off+1] + 0.42f*r2[off+1] + 1.07f*(v1 + bias[c0+1]);
                } else if (MODE == 2) {
                    C[off] = tfr(v0*scale); C[off+1] = tfr(v1*scale);
                } else {
                    const size_t go = (size_t)rr * CL + c0;
                    C[off]   = v0*scale + gbp[go];
                    C[off+1] = v1*scale + gbp[go+1];
                }
            }
        }
    }
}

// ---------------- attn_out = P @ V on tensor cores (per head, causal) ----------------
__global__ __launch_bounds__(256, 2) void attn_pv() {
    const int l0 = blockIdx.x * 128;
    const int h = blockIdx.y, b = blockIdx.z;
    const float* S = g_S + ((size_t)(b * CNH + h)) * CL * CL;
    const float* V = g_V + (size_t)b * CL * CD + h * CHD;
    float* O = g_ao + (size_t)b * CL * CD + h * CHD;

    extern __shared__ float sm[];
    const int STG = 4608 + 2304;
    float* Ssm[2] = { sm, sm + STG };
    float* Vsm[2] = { sm + 4608, sm + STG + 4608 };

    const int t = threadIdx.x;
    const int wid = t >> 5, lane = t & 31;
    const int wm = wid * 16;
    const int g = lane >> 2, tig = lane & 3;

    float acc[8][4];
#pragma unroll
    for (int j = 0; j < 8; j++)
#pragma unroll
        for (int q = 0; q < 4; q++) acc[j][q] = 0.f;

    auto loadS = [&](float* s, int k0) {
        int r = t >> 3, k4 = (t & 7) * 4;
#pragma unroll
        for (int it = 0; it < 4; it++)
            cpa16(s + (r + it*32)*36 + k4,
                  S + (size_t)(l0 + r + it*32) * CL + k0 + k4);
    };
    auto loadV = [&](float* s, int k0) {
        int kr = t >> 4, n4 = (t & 15) * 4;
#pragma unroll
        for (int it = 0; it < 2; it++)
            cpa16(s + (kr + it*16)*72 + n4,
                  V + (size_t)(k0 + kr + it*16) * CD + n4);
    };

    const int NT = (l0 + 128) >> 5;
    loadS(Ssm[0], 0); loadV(Vsm[0], 0);
    asm volatile("cp.async.commit_group;");

    for (int kt = 0; kt < NT; kt++) {
        if (kt + 1 < NT) {
            loadS(Ssm[(kt+1)&1], (kt+1)*32);
            loadV(Vsm[(kt+1)&1], (kt+1)*32);
            asm volatile("cp.async.commit_group;");
            asm volatile("cp.async.wait_group 1;");
        } else {
            asm volatile("cp.async.wait_group 0;");
        }
        __syncthreads();
        const unsigned* Ab = (const unsigned*)Ssm[kt&1];
        const unsigned* Bb = (const unsigned*)Vsm[kt&1];
#pragma unroll
        for (int ks = 0; ks < 4; ks++) {
            const int k = ks * 8;
            unsigned af[4];
            const unsigned* ap = Ab + (wm + g)*36 + k + tig;
            af[0] = ap[0];
            af[1] = ap[8*36];
            af[2] = ap[4];
            af[3] = ap[8*36 + 4];
            unsigned bf[8][2];
#pragma unroll
            for (int j = 0; j < 8; j++) {
                const unsigned* bp = Bb + (k + tig)*72 + 8*j + g;
                bf[j][0] = bp[0];
                bf[j][1] = bp[4*72];
            }
#pragma unroll
            for (int j = 0; j < 8; j++)
                mma8(acc[j], af, bf[j]);
        }
        __syncthreads();
    }
#pragma unroll
    for (int j = 0; j < 8; j++) {
        const int c0 = 8*j + 2*tig;
#pragma unroll
        for (int h2 = 0; h2 < 2; h2++) {
            const int rr = l0 + wm + g + h2*8;
            O[(size_t)rr * CD + c0]     = acc[j][h2*2];
            O[(size_t)rr * CD + c0 + 1] = acc[j][h2*2 + 1];
        }
    }
}

// ---------------- rope helpers ----------------
__global__ void inv_kernel() {
    int d = threadIdx.x;
    double e = (double)(2 * d) / (double)CD;
    g_invd[d]        = pow(1.6180339887498948482, -e);
    g_invd[512 + d]  = pow(1618.0, -e);
    g_invd[1024 + d] = pow(16180.0, -e);
}

__device__ __forceinline__ void rope_cs(double inv, int t, float* c, float* s) {
    double ang = (double)t * inv;
    double k = floor(ang * 0.15915494309189533576888376337251436);
    float a = (float)(ang - k * 6.28318530717958647692528676655900577);
    sincosf(a, s, c);
}

// ---------------- causal cumulative mean: 3-phase parallel scan ----------------
__global__ void poolA_kernel(const float* __restrict__ z) {
    const int c = blockIdx.x, b = blockIdx.y;     // chunk 0..31 (64 rows), batch
    const int t = threadIdx.x;                    // 256: each thread one float4 column
    const float4* zp = (const float4*)(z + ((size_t)b * CL + c * 64) * CD);
    float4* pp = (float4*)(g_pool + ((size_t)b * CL + c * 64) * CD);
    float4 acc = make_float4(0.f, 0.f, 0.f, 0.f);
    for (int r = 0; r < 64; r++) {
        float4 v = zp[r * 256 + t];
        acc.x += v.x; acc.y += v.y; acc.z += v.z; acc.w += v.w;
        pp[r * 256 + t] = acc;                    // local (chunk) cumsum, raw
    }
    ((float4*)g_csum)[((size_t)b * 32 + c) * 256 + t] = acc;
}
__global__ void poolB_kernel() {
    int idx = blockIdx.x * 256 + threadIdx.x;     // (b,d): 2048 threads
    int b = idx >> 10, d = idx & 1023;
    float run = 0.f;
    for (int c = 0; c < 32; c++) {
        size_t o = ((size_t)b * 32 + c) * CD + d;
        float v = g_csum[o];
        g_csum[o] = run;                          // exclusive prefix
        run += v;
    }
}
__global__ void poolC_kernel() {
    size_t idx = (size_t)blockIdx.x * 256 + threadIdx.x;   // f4 over CM*CD/4
    int row = (int)(idx >> 8);
    int f4 = (int)(idx & 255);
    int b = row >> 11, l = row & (CL - 1), c = l >> 6;
    float4 off = ((const float4*)g_csum)[((size_t)(b * 32 + c)) * 256 + f4];
    float4 v = ((float4*)g_pool)[idx];
    float inv = 1.f / (float)(l + 1);
    v.x = tfr((v.x + off.x) * inv);
    v.y = tfr((v.y + off.y) * inv);
    v.z = tfr((v.z + off.z) * inv);
    v.w = tfr((v.w + off.w) * inv);
    ((float4*)g_pool)[idx] = v;
}

// ---------------- gate/nu epilogues (hidden computed by tc_gemm) ----------------
__global__ __launch_bounds__(256) void gate2_kernel(
    const float* __restrict__ hid, const float* __restrict__ w2,
    const float* __restrict__ b2)
{
    int row = blockIdx.x * 8 + (threadIdx.x >> 5);
    int lane = threadIdx.x & 31;
    const float* hr = hid + (size_t)row * CHGATE;
    float acc = 0.f;
#pragma unroll
    for (int j = 0; j < 8; j++) {
        int c = lane + j * 32;
        float x = hr[c];
        float h = 0.5f * x * (1.f + erff(x * 0.7071067811865476f));
        acc += h * w2[c];
    }
#pragma unroll
    for (int o = 16; o > 0; o >>= 1) acc += __shfl_xor_sync(~0u, acc, o);
    if (lane == 0) {
        float y = acc + b2[0];
        g_gate[row] = 1.f / (1.f + expf(-y));
    }
}
__global__ __launch_bounds__(256) void nu2_kernel(
    const float* __restrict__ hid, const float* __restrict__ w2,
    const float* __restrict__ b2,
    const float* __restrict__ nu_diff, const float* __restrict__ nu_adv)
{
    int row = blockIdx.x * 8 + (threadIdx.x >> 5);
    int lane = threadIdx.x & 31;
    const float* hr = hid + (size_t)row * CHNU;
    float acc = 0.f;
#pragma unroll
    for (int j = 0; j < 4; j++) {
        int c = lane + j * 32;
        acc += tanhf(hr[c]) * w2[c];
    }
#pragma unroll
    for (int o = 16; o > 0; o >>= 1) acc += __shfl_xor_sync(~0u, acc, o);
    if (lane == 0) {
        g_nu[row] = fabsf(nu_diff[0]) + tanhf(acc + b2[0]) * fabsf(nu_adv[0]);
    }
}

// ---------------- RoPE (in-place on Q,K; blended gate; rounded out) ----------------
__global__ void rope_qk_kernel() {
    int idx = blockIdx.x * blockDim.x + threadIdx.x;
    if (idx >= CM * 512) return;
    int d = idx & 511;
    int row = idx >> 9;
    int t = row & (CL - 1);
    float g = g_gate[row];
    float cf, sf, c2, s2;
    rope_cs(g_invd[d], t, &cf, &sf);
    rope_cs(g_invd[512 + d], t, &c2, &s2);
    float c = g * cf + (1.f - g) * c2;
    float s = g * sf + (1.f - g) * s2;
    size_t lo = (size_t)row * CD + d, hi = lo + 512;
    float ql = g_Q[lo], qh = g_Q[hi];
    g_Q[lo] = tfr(ql * c - qh * s);
    g_Q[hi] = tfr(qh * c + ql * s);
    float kl = g_K[lo], kh = g_K[hi];
    g_K[lo] = tfr(kl * c - kh * s);
    g_K[hi] = tfr(kh * c + kl * s);
}

__global__ void rope_glu_kernel(const float* __restrict__ z) {
    int idx = blockIdx.x * blockDim.x + threadIdx.x;
    if (idx >= CM * 512) return;
    int d = idx & 511;
    int row = idx >> 9;
    int t = row & (CL - 1);
    float c, s;
    rope_cs(g_invd[1024 + d], t, &c, &s);
    size_t lo = (size_t)row * CD + d, hi = lo + 512;
    float xl = z[lo], xh = z[hi];
    g_zglu[lo] = tfr(xl * c - xh * s);
    g_zglu[hi] = tfr(xh * c + xl * s);
}

// ---------------- fused causal softmax (16 heads) + head-mean, float4 ----------------
__global__ __launch_bounds__(256) void smaw_kernel(float* __restrict__ aw) {
    const int l = blockIdx.x;
    const int b = blockIdx.y;
    const int n = l + 1;
    const int bound = ((l >> 7) + 1) << 7;     // 128-block boundary for attn_pv
    const int tid = threadIdx.x;
    const int lane = tid & 31, wid = tid >> 5;
    __shared__ float red[8];
    float4 awacc[2];
    awacc[0] = make_float4(0.f, 0.f, 0.f, 0.f);
    awacc[1] = make_float4(0.f, 0.f, 0.f, 0.f);
    const float NEG = -3.4e38f;

    for (int h = 0; h < CNH; h++) {
        float* row = g_S + ((size_t)(b * CNH + h) * CL + l) * CL;
        float4* row4 = (float4*)row;
        float4 v[2];
        float mx = NEG;
#pragma unroll
        for (int ii = 0; ii < 2; ii++) {
            int f4 = tid + ii * 256;
            int c0 = f4 * 4;
            if (c0 < n) {
                float4 tv = row4[f4];
                if (c0 + 1 >= n) tv.y = NEG;
                if (c0 + 2 >= n) tv.z = NEG;
                if (c0 + 3 >= n) tv.w = NEG;
                v[ii] = tv;
            } else {
                v[ii] = make_float4(NEG, NEG, NEG, NEG);
            }
            mx = fmaxf(mx, fmaxf(fmaxf(v[ii].x, v[ii].y), fmaxf(v[ii].z, v[ii].w)));
        }
#pragma unroll
        for (int o = 16; o > 0; o >>= 1) mx = fmaxf(mx, __shfl_xor_sync(~0u, mx, o));
        if (lane == 0) red[wid] = mx;
        __syncthreads();
        mx = red[0];
#pragma unroll
        for (int w = 1; w < 8; w++) mx = fmaxf(mx, red[w]);
        __syncthreads();

        float sum = 0.f;
#pragma unroll
        for (int ii = 0; ii < 2; ii++) {
            v[ii].x = expf(v[ii].x - mx);
            v[ii].y = expf(v[ii].y - mx);
            v[ii].z = expf(v[ii].z - mx);
            v[ii].w = expf(v[ii].w - mx);
            sum += v[ii].x + v[ii].y + v[ii].z + v[ii].w;
        }
#pragma unroll
        for (int o = 16; o > 0; o >>= 1) sum += __shfl_xor_sync(~0u, sum, o);
        if (lane == 0) red[wid] = sum;
        __syncthreads();
        sum = red[0];
#pragma unroll
        for (int w = 1; w < 8; w++) sum += red[w];
        __syncthreads();
        float rinv = 1.f / sum;

#pragma unroll
        for (int ii = 0; ii < 2; ii++) {
            int f4 = tid + ii * 256;
            int c0 = f4 * 4;
            if (c0 < bound) {
                float4 p;
                p.x = v[ii].x * rinv; p.y = v[ii].y * rinv;
                p.z = v[ii].z * rinv; p.w = v[ii].w * rinv;
                awacc[ii].x += p.x; awacc[ii].y += p.y;
                awacc[ii].z += p.z; awacc[ii].w += p.w;
                float4 pr;
                pr.x = tfr(p.x); pr.y = tfr(p.y); pr.z = tfr(p.z); pr.w = tfr(p.w);
                row4[f4] = pr;
            }
        }
    }
    float4* awr4 = (float4*)(aw + ((size_t)b * CL + l) * CL);
    const float s16 = 1.f / CNH;
#pragma unroll
    for (int ii = 0; ii < 2; ii++) {
        int f4 = tid + ii * 256;
        float4 o;
        o.x = awacc[ii].x * s16; o.y = awacc[ii].y * s16;
        o.z = awacc[ii].z * s16; o.w = awacc[ii].w * s16;
        awr4[f4] = o;
    }
}

// ---------------- bilinear * (-nu) + LayerNorm (rounded out) ----------------
__global__ __launch_bounds__(256) void bilin_ln_kernel(
    const float* __restrict__ ln_w, const float* __restrict__ ln_b)
{
    int row = blockIdx.x;
    int tid = threadIdx.x;
    size_t off = (size_t)row * CD;
    float nu = g_nu[row];
    __shared__ float red[256], red2[256];
    float a[4]; float s = 0.f, s2 = 0.f;
#pragma unroll
    for (int i = 0; i < 4; i++) {
        int d = tid + i * 256;
        float v = -nu * g_U[off + d] * g_Gg[off + d];
        a[i] = v; s += v; s2 += v * v;
    }
    red[tid] = s; red2[tid] = s2; __syncthreads();
    for (int st = 128; st > 0; st >>= 1) {
        if (tid < st) { red[tid] += red[tid + st]; red2[tid] += red2[tid + st]; }
        __syncthreads();
    }
    float mu = red[0] * (1.f / CD);
    float var = red2[0] * (1.f / CD) - mu * mu;
    float rstd = rsqrtf(var + 1e-5f);
#pragma unroll
    for (int i = 0; i < 4; i++) {
        int d = tid + i * 256;
        g_U[off + d] = tfr((a[i] - mu) * rstd * ln_w[d] + ln_b[d]);
    }
}

// ---------------- launcher ----------------
extern "C" void kernel_launch(void* const* d_in, const int* in_sizes, int n_in,
                              void* d_out, int out_size) {
    (void)in_sizes; (void)n_in; (void)out_size;
    const float* z     = (const float*)d_in[0];
    const float* Wq    = (const float*)d_in[1];
    const float* bq    = (const float*)d_in[2];
    const float* Wk    = (const float*)d_in[3];
    const float* bk    = (const float*)d_in[4];
    const float* Wv    = (const float*)d_in[5];
    const float* bv    = (const float*)d_in[6];
    const float* Wcoh  = (const float*)d_in[7];
    const float* gamma = (const float*)d_in[8];
    const float* rg_w1 = (const float*)d_in[9];
    const float* rg_b1 = (const float*)d_in[10];
    const float* rg_w2 = (const float*)d_in[11];
    const float* rg_b2 = (const float*)d_in[12];
    const float* nu_diff = (const float*)d_in[13];
    const float* nu_adv  = (const float*)d_in[14];
    const float* nu_w1 = (const float*)d_in[15];
    const float* nu_b1 = (const float*)d_in[16];
    const float* nu_w2 = (const float*)d_in[17];
    const float* nu_b2 = (const float*)d_in[18];
    const float* Wu    = (const float*)d_in[19];
    const float* bu    = (const float*)d_in[20];
    const float* Wg    = (const float*)d_in[21];
    const float* bg    = (const float*)d_in[22];
    const float* ln_w  = (const float*)d_in[23];
    const float* ln_b  = (const float*)d_in[24];
    const float* Cw    = (const float*)d_in[25];
    const float* Cb    = (const float*)d_in[26];

    float* out_z  = (float*)d_out;
    float* out_aw = out_z + (size_t)CM * CD;

    void* tmp;
    cudaGetSymbolAddress(&tmp, g_pool); float* pPool = (float*)tmp;
    cudaGetSymbolAddress(&tmp, g_Q);    float* pQ    = (float*)tmp;
    cudaGetSymbolAddress(&tmp, g_K);    float* pK    = (float*)tmp;
    cudaGetSymbolAddress(&tmp, g_V);    float* pV    = (float*)tmp;
    cudaGetSymbolAddress(&tmp, g_gk);   float* pGk   = (float*)tmp;
    cudaGetSymbolAddress(&tmp, g_zglu); float* pZg   = (float*)tmp;
    cudaGetSymbolAddress(&tmp, g_U);    float* pU    = (float*)tmp;
    cudaGetSymbolAddress(&tmp, g_Gg);   float* pG    = (float*)tmp;
    cudaGetSymbolAddress(&tmp, g_ao);   float* pAo   = (float*)tmp;
    cudaGetSymbolAddress(&tmp, g_zr);   float* pZr   = (float*)tmp;
    cudaGetSymbolAddress(&tmp, g_Wr);   float* pWr   = (float*)tmp;
    cudaGetSymbolAddress(&tmp, g_gb);   float* pGb   = (float*)tmp;
    cudaGetSymbolAddress(&tmp, g_S);    float* pS    = (float*)tmp;

    float* rWq = pWr;
    float* rWk = pWr + 1048576;
    float* rWv = pWr + 2*1048576;
    float* rWc = pWr + 3*1048576;
    float* rWu = pWr + 4*1048576;
    float* rWg = pWr + 5*1048576;
    float* rCw = pWr + 6*1048576;
    float* rG1 = pWr + 7*1048576;            // rg_w1 (1024x256)
    float* rN1 = pWr + 7*1048576 + 262144;   // nu_w1 (1024x128)

    float* pHg = pS;                          // gate hidden (CM x 256) in g_S scratch
    float* pHn = pS + (size_t)CM * CHGATE;    // nu hidden   (CM x 128)

    const size_t SMEM  = 2 * 9216 * sizeof(float);   // 73728
    const size_t SMEMP = 2 * 6912 * sizeof(float);   // 55296 (attn_pv)
    cudaFuncSetAttribute(tc_gemm<0,0,0>, cudaFuncAttributeMaxDynamicSharedMemorySize, (int)SMEM);
    cudaFuncSetAttribute(tc_gemm<0,0,1>, cudaFuncAttributeMaxDynamicSharedMemorySize, (int)SMEM);
    cudaFuncSetAttribute(tc_gemm<0,1,0>, cudaFuncAttributeMaxDynamicSharedMemorySize, (int)SMEM);
    cudaFuncSetAttribute(tc_gemm<1,2,0>, cudaFuncAttributeMaxDynamicSharedMemorySize, (int)SMEM);
    cudaFuncSetAttribute(tc_gemm<1,3,0>, cudaFuncAttributeMaxDynamicSharedMemorySize, (int)SMEM);
    cudaFuncSetAttribute(attn_pv, cudaFuncAttributeMaxDynamicSharedMemorySize, (int)SMEMP);

    dim3 gmain(CD / 128, CM / 128, 1);   // (8, 32)

    inv_kernel<<<1, 512>>>();

    RndArgs ra;
    ra.src[0]=Wq;   ra.dst[0]=rWq; ra.n[0]=1048576;
    ra.src[1]=Wk;   ra.dst[1]=rWk; ra.n[1]=1048576;
    ra.src[2]=Wv;   ra.dst[2]=rWv; ra.n[2]=1048576;
    ra.src[3]=Wcoh; ra.dst[3]=rWc; ra.n[3]=1048576;
    ra.src[4]=Wu;   ra.dst[4]=rWu; ra.n[4]=1048576;
    ra.src[5]=Wg;   ra.dst[5]=rWg; ra.n[5]=1048576;
    ra.src[6]=Cw;   ra.dst[6]=rCw; ra.n[6]=1048576;
    ra.src[7]=z;    ra.dst[7]=pZr; ra.n[7]=CM*CD;
    ra.src[8]=rg_w1;ra.dst[8]=rG1; ra.n[8]=262144;
    roundN_kernel<<<dim3(256, 9), 256>>>(ra);
    // nu_w1 separately (10th region)
    RndArgs rb;
    rb.src[0]=nu_w1; rb.dst[0]=rN1; rb.n[0]=131072;
    for (int i = 1; i < 9; i++) { rb.src[i]=nu_w1; rb.dst[i]=rN1; rb.n[i]=0; }
    roundN_kernel<<<dim3(64, 1), 256>>>(rb);

    poolA_kernel<<<dim3(32, CB), 256>>>(z);
    poolB_kernel<<<8, 256>>>();
    poolC_kernel<<<CM, 256>>>();

    tc_gemm<0,0,0><<<gmain, 256, SMEM>>>(pZr, rWq, bq, pQ, CD, CD, CD, CD,
        0,0,0,0,0,0,1, nullptr, nullptr, nullptr, nullptr);
    tc_gemm<0,0,1><<<gmain, 256, SMEM>>>(pZr, rWk, bk, pK, CD, CD, CD, CD,
        0,0,0,0,0,0,1, nullptr, nullptr, nullptr, nullptr);
    tc_gemm<0,0,1><<<gmain, 256, SMEM>>>(pZr, rWv, bv, pV, CD, CD, CD, CD,
        0,0,0,0,0,0,1, nullptr, nullptr, nullptr, nullptr);
    tc_gemm<0,0,1><<<gmain, 256, SMEM>>>(pPool, rWc, nullptr, pGk, CD, CD, CD, CD,
        0,0,0,0,0,0,1, nullptr, nullptr, nullptr, nullptr);

    // gate / nu hidden layers on tensor cores (output into g_S scratch)
    tc_gemm<0,0,0><<<dim3(CHGATE/128, CM/128, 1), 256, SMEM>>>(pPool, rG1, rg_b1, pHg,
        CD, CD, CHGATE, CHGATE, 0,0,0,0,0,0,1, nullptr, nullptr, nullptr, nullptr);
    tc_gemm<0,0,0><<<dim3(CHNU/128, CM/128, 1), 256, SMEM>>>(pPool, rN1, nu_b1, pHn,
        CD, CD, CHNU, CHNU, 0,0,0,0,0,0,1, nullptr, nullptr, nullptr, nullptr);
    gate2_kernel<<<CM/8, 256>>>(pHg, rg_w2, rg_b2);
    nu2_kernel<<<CM/8, 256>>>(pHn, nu_w2, nu_b2, nu_diff, nu_adv);

    tc_gemm<1,2,0><<<dim3(CL/128, CL/128, CB), 256, SMEM>>>(pGk, pK, nullptr, pGb,
        CD, CD, CD, CL,
        (long)CL*CD, 0, (long)CL*CD, 0, (long)CL*CL, 0, 1,
        nullptr, nullptr, gamma, nullptr);

    rope_qk_kernel<<<(CM * 512) / 256, 256>>>();
    rope_glu_kernel<<<(CM * 512) / 256, 256>>>(z);

    tc_gemm<0,0,0><<<gmain, 256, SMEM>>>(pZg, rWu, bu, pU, CD, CD, CD, CD,
        0,0,0,0,0,0,1, nullptr, nullptr, nullptr, nullptr);
    tc_gemm<0,0,0><<<gmain, 256, SMEM>>>(pZg, rWg, bg, pG, CD, CD, CD, CD,
        0,0,0,0,0,0,1, nullptr, nullptr, nullptr, nullptr);

    tc_gemm<1,3,0><<<dim3(CL/128, CL/128, CB*CNH), 256, SMEM>>>(pQ, pK, nullptr, pS,
        CHD, CD, CD, CL,
        (long)CL*CD, CHD, (long)CL*CD, CHD, (long)CL*CL, (long)CL*CL, CNH,
        nullptr, nullptr, nullptr, pGb);

    smaw_kernel<<<dim3(CL, CB), 256>>>(out_aw);
    attn_pv<<<dim3(CL/128, CNH, CB), 256, SMEMP>>>();

    bilin_ln_kernel<<<CM, 256>>>(ln_w, ln_b);
    tc_gemm<0,1,0><<<gmain, 256, SMEM>>>(pU, rCw, Cb, out_z, CD, CD, CD, CD,
        0,0,0,0,0,0,1, z, pAo, nullptr, nullptr);
}